// round 4
// baseline (speedup 1.0000x reference)
#include <cuda_runtime.h>
#include <math.h>

#define T_SEQ 2048
#define BATCH 4
#define DIN   512
#define DOUT  256
#define NROWS 16384   // 2*BATCH*T_SEQ (q rows then k rows)

// Scratch (static __device__ — no allocation)
__device__ float g_h1[NROWS * DOUT];
__device__ float g_h2[NROWS * DOUT];
__device__ float g_A[NROWS * DOUT];
__device__ float g_B[NROWS * DOUT];

// ---------------------------------------------------------------------------
// helpers
// ---------------------------------------------------------------------------
__device__ __forceinline__ float f_ex2(float x) {
    float y; asm("ex2.approx.ftz.f32 %0, %1;" : "=f"(y) : "f"(x)); return y;
}
__device__ __forceinline__ float f_lg2(float x) {
    float y; asm("lg2.approx.ftz.f32 %0, %1;" : "=f"(y) : "f"(x)); return y;
}
__device__ __forceinline__ float f_rcp(float x) {
    float y; asm("rcp.approx.ftz.f32 %0, %1;" : "=f"(y) : "f"(x)); return y;
}
__device__ __forceinline__ void mma_tf32(
    float& c0, float& c1, float& c2, float& c3,
    unsigned a0, unsigned a1, unsigned a2, unsigned a3,
    unsigned b0, unsigned b1)
{
    asm("mma.sync.aligned.m16n8k8.row.col.f32.tf32.tf32.f32 "
        "{%0,%1,%2,%3}, {%4,%5,%6,%7}, {%8,%9}, {%0,%1,%2,%3};"
        : "+f"(c0), "+f"(c1), "+f"(c2), "+f"(c3)
        : "r"(a0), "r"(a1), "r"(a2), "r"(a3), "r"(b0), "r"(b1));
}

#define LN2   0.69314718056f
#define RLN2  1.44269504089f

// ln Gamma(x), x in [0.01, 210]: shift-by-4 + 2-term Stirling (err < 1e-6)
__device__ __forceinline__ float lgamma_fast(float x) {
    float p  = x * (x + 1.f) * (x + 2.f) * (x + 3.f);
    float y  = x + 4.f;
    float ly = f_lg2(y) * LN2;
    float iy = f_rcp(y);
    float c  = iy * fmaf(-0.00277777778f, iy * iy, 0.08333333333f);
    return fmaf(y - 0.5f, ly, -y) + 0.91893853320f + c - f_lg2(p) * LN2;
}
__device__ __forceinline__ float softplus_fast(float x) {
    float e = f_ex2(-fabsf(x) * RLN2);
    return fmaxf(x, 0.f) + f_lg2(1.f + e) * LN2;
}
__device__ __forceinline__ float kuma_out(float ar, float br) {
    const float K_T0 = -3.58496250072f;   // log2(1/12)
    const float K_T1 = -0.12553088208f;   // log2(11/12)
    float a  = fminf(fmaxf(softplus_fast(ar), 0.01f), 100.f);
    float bb = fminf(fmaxf(softplus_fast(br), 0.01f), 100.f);
    float u0 = f_ex2(a * K_T0);
    float u1 = f_ex2(a * K_T1);
    float E0 = f_ex2(bb * f_lg2(1.f - u0));  // 1 - p0
    float p1 = f_ex2(bb * f_lg2(1.f - u1));
    float pc = E0 - p1;
    float g  = 1.f + f_rcp(a);
    float lm = lgamma_fast(g) + lgamma_fast(bb) - lgamma_fast(g + bb);
    float mean = bb * f_ex2(lm * RLN2);
    mean = fminf(fmaxf(fmaf(1.2f, mean, -0.1f), 0.f), 1.f);
    float zo = (1.f - E0 > p1) ? 0.f : 1.f;
    return (pc < 0.5f) ? zo : mean;
}

// k-permutation within each 8-group: pair (t4, t4+4) becomes adjacent.
// kk -> (kk & ~7) + (kk&3)*2 + ((kk>>2)&1)
__device__ __forceinline__ int kperm(int kk) {
    return (kk & ~7) + ((kk & 3) << 1) + ((kk >> 2) & 1);
}

// ---------------------------------------------------------------------------
// tf32 MLP GEMM: C[16384,256] = relu(X @ W + bias), dual weight set.
// grid = (8, 128): x = set*4 + colblock(64). Block tile 128x64, BK=32.
// 8 warps as 4(m)x2(n), warp tile 32x32. k-permuted smem, LDS.64 fragments,
// register double-buffered global loads.
// ---------------------------------------------------------------------------
__global__ void __launch_bounds__(256) mlp_tf32_kernel(
    const float* __restrict__ Xq1, const float* __restrict__ Xk1,
    const float* __restrict__ W1,  const float* __restrict__ bias1, float* __restrict__ C1,
    const float* __restrict__ Xq2, const float* __restrict__ Xk2,
    const float* __restrict__ W2,  const float* __restrict__ bias2, float* __restrict__ C2,
    int K)
{
    __shared__ unsigned As[128][34];  // [m][k-perm], pad to 34
    __shared__ unsigned Bs[64][34];   // [n][k-perm]

    int set = blockIdx.x >> 2;
    int bn  = blockIdx.x & 3;
    long rbase = (long)blockIdx.y * 128;

    const float* Xq   = set ? Xq2 : Xq1;
    const float* Xk   = set ? Xk2 : Xk1;
    const float* W    = set ? W2  : W1;
    const float* bias = set ? bias2 : bias1;
    float*       C    = set ? C2  : C1;

    const float* X;
    if (Xk != nullptr && rbase >= 8192) X = Xk + (rbase - 8192) * (long)K;
    else                                X = Xq + rbase * (long)K;

    int tid = threadIdx.x;
    int wid = tid >> 5, lane = tid & 31;
    int wm  = wid >> 1, wn = wid & 1;
    int g   = lane >> 2, t4 = lane & 3;

    // per-thread global-load coords
    int rX[4], kqX[4];
#pragma unroll
    for (int it = 0; it < 4; it++) {
        int qi = tid + it * 256;          // 1024 quads: 128 rows x 8 quads
        rX[it]  = qi >> 3;
        kqX[it] = (qi & 7) * 4;
    }
    int kW[2], cW[2];
#pragma unroll
    for (int it = 0; it < 2; it++) {
        int qi = tid + it * 256;          // 512 quads: 32 k x 16 quads
        kW[it] = qi >> 4;
        cW[it] = (qi & 15) * 4;
    }

    float acc[2][4][4];
#pragma unroll
    for (int mt = 0; mt < 2; mt++)
#pragma unroll
        for (int nt = 0; nt < 4; nt++)
#pragma unroll
            for (int c = 0; c < 4; c++) acc[mt][nt][c] = 0.f;

    float4 xb[4], wb[2];

    // prologue
#pragma unroll
    for (int it = 0; it < 4; it++)
        xb[it] = *(const float4*)(X + (long)rX[it] * K + kqX[it]);
#pragma unroll
    for (int it = 0; it < 2; it++)
        wb[it] = *(const float4*)(W + (long)kW[it] * DOUT + bn * 64 + cW[it]);

    for (int k0 = 0; k0 < K; k0 += 32) {
        // store staged regs -> smem (k-permuted)
#pragma unroll
        for (int it = 0; it < 4; it++) {
            int grp = kqX[it] & ~7;
            int sub = (kqX[it] >> 2) & 1;
            unsigned* p = &As[rX[it]][grp + sub];
            p[0] = __float_as_uint(xb[it].x);
            p[2] = __float_as_uint(xb[it].y);
            p[4] = __float_as_uint(xb[it].z);
            p[6] = __float_as_uint(xb[it].w);
        }
#pragma unroll
        for (int it = 0; it < 2; it++) {
            int pc = kperm(kW[it]);
            Bs[cW[it] + 0][pc] = __float_as_uint(wb[it].x);
            Bs[cW[it] + 1][pc] = __float_as_uint(wb[it].y);
            Bs[cW[it] + 2][pc] = __float_as_uint(wb[it].z);
            Bs[cW[it] + 3][pc] = __float_as_uint(wb[it].w);
        }
        __syncthreads();

        // prefetch next tile into registers
        bool notlast = (k0 + 32 < K);
        if (notlast) {
#pragma unroll
            for (int it = 0; it < 4; it++)
                xb[it] = *(const float4*)(X + (long)rX[it] * K + k0 + 32 + kqX[it]);
#pragma unroll
            for (int it = 0; it < 2; it++)
                wb[it] = *(const float4*)(W + (long)(k0 + 32 + kW[it]) * DOUT + bn * 64 + cW[it]);
        }

        // compute
#pragma unroll
        for (int k8 = 0; k8 < 4; k8++) {
            int col = k8 * 8 + t4 * 2;
            uint2 alo[2], ahi[2];
#pragma unroll
            for (int mt = 0; mt < 2; mt++) {
                int r0 = wm * 32 + mt * 16;
                alo[mt] = *(const uint2*)&As[r0 + g    ][col];
                ahi[mt] = *(const uint2*)&As[r0 + g + 8][col];
            }
#pragma unroll
            for (int nt = 0; nt < 4; nt++) {
                uint2 bv = *(const uint2*)&Bs[wn * 32 + nt * 8 + g][col];
#pragma unroll
                for (int mt = 0; mt < 2; mt++)
                    mma_tf32(acc[mt][nt][0], acc[mt][nt][1],
                             acc[mt][nt][2], acc[mt][nt][3],
                             alo[mt].x, ahi[mt].x, alo[mt].y, ahi[mt].y,
                             bv.x, bv.y);
            }
        }
        __syncthreads();
    }

    // epilogue: bias + relu
#pragma unroll
    for (int mt = 0; mt < 2; mt++) {
#pragma unroll
        for (int rr = 0; rr < 2; rr++) {
            long row = rbase + wm * 32 + mt * 16 + g + rr * 8;
#pragma unroll
            for (int nt = 0; nt < 4; nt++) {
                int col = bn * 64 + wn * 32 + nt * 8 + t4 * 2;
                float2 o;
                o.x = fmaxf(acc[mt][nt][rr*2+0] + bias[col    ], 0.f);
                o.y = fmaxf(acc[mt][nt][rr*2+1] + bias[col + 1], 0.f);
                *(float2*)(C + row * DOUT + col) = o;
            }
        }
    }
}

// ---------------------------------------------------------------------------
// tf32 fused score GEMM (a & b) + HardKuma epilogue.
// grid = (32, 16, 4): block tile 128(t) x 64(s), BK=16, K=256.
// Same k-permuted layout + LDS.64 fragments + reg double buffering.
// ---------------------------------------------------------------------------
__global__ void __launch_bounds__(256) kuma_attn_tf32_kernel(
    const float* __restrict__ A, const float* __restrict__ Bm,
    const float* __restrict__ dist_emb, float* __restrict__ out)
{
    __shared__ unsigned QA[128][18], QB[128][18];  // [t][k-perm]
    __shared__ unsigned KA[64][18],  KB[64][18];   // [s][k-perm]
    __shared__ float sdist[23];

    int b  = blockIdx.z;
    int bt = blockIdx.y * 128;
    int bs = blockIdx.x * 64;
    int tid = threadIdx.x;
    if (tid < 23) sdist[tid] = dist_emb[tid];

    int wid = tid >> 5, lane = tid & 31;
    int wm  = wid >> 1, wn = wid & 1;
    int g   = lane >> 2, t4 = lane & 3;

    const float* qa = A  + ((long)b * T_SEQ + bt) * DOUT;
    const float* ka = A  + ((long)(8192 + b * T_SEQ) + bs) * DOUT;
    const float* qb = Bm + ((long)b * T_SEQ + bt) * DOUT;
    const float* kb = Bm + ((long)(8192 + b * T_SEQ) + bs) * DOUT;

    // global-load coords
    int rQ[2], kqQ[2];
#pragma unroll
    for (int it = 0; it < 2; it++) {
        int qi = tid + it * 256;          // 512 quads: 128 rows x 4 quads
        rQ[it]  = qi >> 2;
        kqQ[it] = (qi & 3) * 4;
    }
    int rK = tid >> 2, kqK = (tid & 3) * 4;   // 256 quads: 64 rows x 4 quads

    float accA[2][4][4], accB[2][4][4];
#pragma unroll
    for (int mt = 0; mt < 2; mt++)
#pragma unroll
        for (int nt = 0; nt < 4; nt++)
#pragma unroll
            for (int c = 0; c < 4; c++) { accA[mt][nt][c] = 0.f; accB[mt][nt][c] = 0.f; }

    float4 qav[2], qbv[2], kav, kbv;
#pragma unroll
    for (int it = 0; it < 2; it++) {
        qav[it] = *(const float4*)(qa + (long)rQ[it] * DOUT + kqQ[it]);
        qbv[it] = *(const float4*)(qb + (long)rQ[it] * DOUT + kqQ[it]);
    }
    kav = *(const float4*)(ka + (long)rK * DOUT + kqK);
    kbv = *(const float4*)(kb + (long)rK * DOUT + kqK);

    for (int k0 = 0; k0 < DOUT; k0 += 16) {
        // store staged regs -> smem (k-permuted)
#pragma unroll
        for (int it = 0; it < 2; it++) {
            int grp = kqQ[it] & ~7;
            int sub = (kqQ[it] >> 2) & 1;
            unsigned* p = &QA[rQ[it]][grp + sub];
            p[0] = __float_as_uint(qav[it].x); p[2] = __float_as_uint(qav[it].y);
            p[4] = __float_as_uint(qav[it].z); p[6] = __float_as_uint(qav[it].w);
            unsigned* p2 = &QB[rQ[it]][grp + sub];
            p2[0] = __float_as_uint(qbv[it].x); p2[2] = __float_as_uint(qbv[it].y);
            p2[4] = __float_as_uint(qbv[it].z); p2[6] = __float_as_uint(qbv[it].w);
        }
        {
            int grp = kqK & ~7;
            int sub = (kqK >> 2) & 1;
            unsigned* p = &KA[rK][grp + sub];
            p[0] = __float_as_uint(kav.x); p[2] = __float_as_uint(kav.y);
            p[4] = __float_as_uint(kav.z); p[6] = __float_as_uint(kav.w);
            unsigned* p2 = &KB[rK][grp + sub];
            p2[0] = __float_as_uint(kbv.x); p2[2] = __float_as_uint(kbv.y);
            p2[4] = __float_as_uint(kbv.z); p2[6] = __float_as_uint(kbv.w);
        }
        __syncthreads();

        bool notlast = (k0 + 16 < DOUT);
        if (notlast) {
#pragma unroll
            for (int it = 0; it < 2; it++) {
                qav[it] = *(const float4*)(qa + (long)rQ[it] * DOUT + k0 + 16 + kqQ[it]);
                qbv[it] = *(const float4*)(qb + (long)rQ[it] * DOUT + k0 + 16 + kqQ[it]);
            }
            kav = *(const float4*)(ka + (long)rK * DOUT + k0 + 16 + kqK);
            kbv = *(const float4*)(kb + (long)rK * DOUT + k0 + 16 + kqK);
        }

#pragma unroll
        for (int k8 = 0; k8 < 2; k8++) {
            int col = k8 * 8 + t4 * 2;
            uint2 aAlo[2], aAhi[2], aBlo[2], aBhi[2];
#pragma unroll
            for (int mt = 0; mt < 2; mt++) {
                int r0 = wm * 32 + mt * 16;
                aAlo[mt] = *(const uint2*)&QA[r0 + g    ][col];
                aAhi[mt] = *(const uint2*)&QA[r0 + g + 8][col];
                aBlo[mt] = *(const uint2*)&QB[r0 + g    ][col];
                aBhi[mt] = *(const uint2*)&QB[r0 + g + 8][col];
            }
#pragma unroll
            for (int nt = 0; nt < 4; nt++) {
                int c0 = wn * 32 + nt * 8;
                uint2 bA = *(const uint2*)&KA[c0 + g][col];
                uint2 bB = *(const uint2*)&KB[c0 + g][col];
#pragma unroll
                for (int mt = 0; mt < 2; mt++) {
                    mma_tf32(accA[mt][nt][0], accA[mt][nt][1],
                             accA[mt][nt][2], accA[mt][nt][3],
                             aAlo[mt].x, aAhi[mt].x, aAlo[mt].y, aAhi[mt].y,
                             bA.x, bA.y);
                    mma_tf32(accB[mt][nt][0], accB[mt][nt][1],
                             accB[mt][nt][2], accB[mt][nt][3],
                             aBlo[mt].x, aBhi[mt].x, aBlo[mt].y, aBhi[mt].y,
                             bB.x, bB.y);
                }
            }
        }
        __syncthreads();
    }

    // HardKuma epilogue + store
#pragma unroll
    for (int mt = 0; mt < 2; mt++) {
#pragma unroll
        for (int rr = 0; rr < 2; rr++) {
            int trow = bt + wm * 32 + mt * 16 + g + rr * 8;
#pragma unroll
            for (int nt = 0; nt < 4; nt++) {
                int scol = bs + wn * 32 + nt * 8 + t4 * 2;
                int rel0 = max(-11, min(11, scol     - trow)) + 11;
                int rel1 = max(-11, min(11, scol + 1 - trow)) + 11;
                float rd0 = sdist[rel0], rd1 = sdist[rel1];
                float2 o;
                o.x = kuma_out(accA[mt][nt][rr*2+0] + rd0, accB[mt][nt][rr*2+0] + rd0);
                o.y = kuma_out(accA[mt][nt][rr*2+1] + rd1, accB[mt][nt][rr*2+1] + rd1);
                *(float2*)(out + ((long)b * T_SEQ + trow) * T_SEQ + scol) = o;
            }
        }
    }
}

// ---------------------------------------------------------------------------
extern "C" void kernel_launch(void* const* d_in, const int* in_sizes, int n_in,
                              void* d_out, int out_size)
{
    const float* q    = (const float*)d_in[0];
    const float* k    = (const float*)d_in[1];
    const float* Wa1  = (const float*)d_in[2];
    const float* ba1  = (const float*)d_in[3];
    const float* Wa2  = (const float*)d_in[4];
    const float* ba2  = (const float*)d_in[5];
    const float* Wb1  = (const float*)d_in[6];
    const float* bb1  = (const float*)d_in[7];
    const float* Wb2  = (const float*)d_in[8];
    const float* bb2  = (const float*)d_in[9];
    const float* dist = (const float*)d_in[10];
    float* out = (float*)d_out;

    float *h1, *h2, *A, *Bm;
    cudaGetSymbolAddress((void**)&h1, g_h1);
    cudaGetSymbolAddress((void**)&h2, g_h2);
    cudaGetSymbolAddress((void**)&A,  g_A);
    cudaGetSymbolAddress((void**)&Bm, g_B);

    dim3 blk(256);
    dim3 g1(8, 128);
    mlp_tf32_kernel<<<g1, blk>>>(q, k, Wa1, ba1, h1,
                                 q, k, Wb1, bb1, h2, DIN);
    mlp_tf32_kernel<<<g1, blk>>>(h1, nullptr, Wa2, ba2, A,
                                 h2, nullptr, Wb2, bb2, Bm, DOUT);

    dim3 g2(T_SEQ / 64, T_SEQ / 128, BATCH);
    kuma_attn_tf32_kernel<<<g2, blk>>>(A, Bm, dist, out);
}

// round 5
// speedup vs baseline: 1.8091x; 1.8091x over previous
#include <cuda_runtime.h>

#define T_SEQ 2048
#define BATCH 4
#define DIN   512
#define DOUT  256
#define NROWS 16384   // 2*BATCH*T_SEQ (q rows then k rows)

// Scratch (static __device__ — no allocation)
__device__ float g_h1[NROWS * DOUT];
__device__ float g_h2[NROWS * DOUT];
__device__ float g_A[NROWS * DOUT];
__device__ float g_B[NROWS * DOUT];

// ---------------------------------------------------------------------------
// helpers
// ---------------------------------------------------------------------------
__device__ __forceinline__ float f_ex2(float x) {
    float y; asm("ex2.approx.ftz.f32 %0, %1;" : "=f"(y) : "f"(x)); return y;
}
__device__ __forceinline__ float f_lg2(float x) {
    float y; asm("lg2.approx.ftz.f32 %0, %1;" : "=f"(y) : "f"(x)); return y;
}
__device__ __forceinline__ float f_rcp(float x) {
    float y; asm("rcp.approx.ftz.f32 %0, %1;" : "=f"(y) : "f"(x)); return y;
}
__device__ __forceinline__ void mma_tf32(
    float& c0, float& c1, float& c2, float& c3,
    unsigned a0, unsigned a1, unsigned a2, unsigned a3,
    unsigned b0, unsigned b1)
{
    asm("mma.sync.aligned.m16n8k8.row.col.f32.tf32.tf32.f32 "
        "{%0,%1,%2,%3}, {%4,%5,%6,%7}, {%8,%9}, {%0,%1,%2,%3};"
        : "+f"(c0), "+f"(c1), "+f"(c2), "+f"(c3)
        : "r"(a0), "r"(a1), "r"(a2), "r"(a3), "r"(b0), "r"(b1));
}
__device__ __forceinline__ void cp16(void* d, const void* s) {
    unsigned a = (unsigned)__cvta_generic_to_shared(d);
    asm volatile("cp.async.cg.shared.global [%0], [%1], 16;" :: "r"(a), "l"(s));
}
__device__ __forceinline__ void cp_commit() {
    asm volatile("cp.async.commit_group;");
}
template<int N> __device__ __forceinline__ void cp_wait() {
    asm volatile("cp.async.wait_group %0;" :: "n"(N));
}

#define LN2   0.69314718056f
#define RLN2  1.44269504089f

__device__ __forceinline__ float lgamma_fast(float x) {
    float p  = x * (x + 1.f) * (x + 2.f) * (x + 3.f);
    float y  = x + 4.f;
    float ly = f_lg2(y) * LN2;
    float iy = f_rcp(y);
    float c  = iy * fmaf(-0.00277777778f, iy * iy, 0.08333333333f);
    return fmaf(y - 0.5f, ly, -y) + 0.91893853320f + c - f_lg2(p) * LN2;
}
__device__ __forceinline__ float softplus_fast(float x) {
    float e = f_ex2(-fabsf(x) * RLN2);
    return fmaxf(x, 0.f) + f_lg2(1.f + e) * LN2;
}
__device__ __forceinline__ float kuma_out(float ar, float br) {
    const float K_T0 = -3.58496250072f;   // log2(1/12)
    const float K_T1 = -0.12553088208f;   // log2(11/12)
    float a  = fminf(fmaxf(softplus_fast(ar), 0.01f), 100.f);
    float bb = fminf(fmaxf(softplus_fast(br), 0.01f), 100.f);
    float u0 = f_ex2(a * K_T0);
    float u1 = f_ex2(a * K_T1);
    float E0 = f_ex2(bb * f_lg2(1.f - u0));  // 1 - p0
    float p1 = f_ex2(bb * f_lg2(1.f - u1));
    float pc = E0 - p1;
    float g  = 1.f + f_rcp(a);
    float lm = lgamma_fast(g) + lgamma_fast(bb) - lgamma_fast(g + bb);
    float mean = bb * f_ex2(lm * RLN2);
    mean = fminf(fmaxf(fmaf(1.2f, mean, -0.1f), 0.f), 1.f);
    float zo = (1.f - E0 > p1) ? 0.f : 1.f;
    return (pc < 0.5f) ? zo : mean;
}

// ---------------------------------------------------------------------------
// tf32 MLP GEMM, cp.async 4-stage pipeline.
// C[16384,256] = relu(X @ W + bias), dual weight set.
// grid = (8, 128): x = set*4 + colblock(64). Block tile 128x64, BK=16.
// 8 warps as 4(m)x2(n), warp tile 32x32.
// smem: A[m][k] stride 20 words (conflict-free: bank=4g+t4),
//       B[k][n] stride 68 words (bank=4*t4+g). Both cp.async-native.
// ---------------------------------------------------------------------------
#define MLP_SMEM_BYTES (4 * (128*20 + 16*68) * 4)

__global__ void __launch_bounds__(256) mlp_tf32_kernel(
    const float* __restrict__ Xq1, const float* __restrict__ Xk1,
    const float* __restrict__ W1,  const float* __restrict__ bias1, float* __restrict__ C1,
    const float* __restrict__ Xq2, const float* __restrict__ Xk2,
    const float* __restrict__ W2,  const float* __restrict__ bias2, float* __restrict__ C2,
    int K)
{
    extern __shared__ unsigned sm[];
    unsigned* ASb = sm;                 // 4 stages x 128 x 20
    unsigned* BSb = sm + 4 * 2560;      // 4 stages x 16 x 68

    int set = blockIdx.x >> 2;
    int bn  = blockIdx.x & 3;
    long rbase = (long)blockIdx.y * 128;

    const float* Xq   = set ? Xq2 : Xq1;
    const float* Xk   = set ? Xk2 : Xk1;
    const float* W    = set ? W2  : W1;
    const float* bias = set ? bias2 : bias1;
    float*       C    = set ? C2  : C1;

    const float* X;
    if (Xk != nullptr && rbase >= 8192) X = Xk + (rbase - 8192) * (long)K;
    else                                X = Xq + rbase * (long)K;

    int tid = threadIdx.x;
    int wid = tid >> 5, lane = tid & 31;
    int wm  = wid >> 1, wn = wid & 1;
    int g   = lane >> 2, t4 = lane & 3;

    // copy coords: A tile 128 rows x 4 quads (512 chunks, 2/thread)
    int rA0 = tid >> 2,          qA0 = (tid & 3) * 4;
    int rA1 = (tid + 256) >> 2,  qA1 = ((tid + 256) & 3) * 4;
    // B tile 16 k x 16 quads (256 chunks, 1/thread)
    int kB = tid >> 4, cB = (tid & 15) * 4;

    float acc[2][4][4];
#pragma unroll
    for (int mt = 0; mt < 2; mt++)
#pragma unroll
        for (int nt = 0; nt < 4; nt++)
#pragma unroll
            for (int c = 0; c < 4; c++) acc[mt][nt][c] = 0.f;

    const int ITERS = K >> 4;

#define MLP_ISSUE(ki) do {                                                   \
        int st_ = (ki) & 3; int k0_ = (ki) << 4;                             \
        unsigned* A_ = ASb + st_ * 2560;                                     \
        unsigned* B_ = BSb + st_ * 1088;                                     \
        cp16(A_ + rA0 * 20 + qA0, X + (long)rA0 * K + k0_ + qA0);            \
        cp16(A_ + rA1 * 20 + qA1, X + (long)rA1 * K + k0_ + qA1);            \
        cp16(B_ + kB * 68 + cB, W + (long)(k0_ + kB) * DOUT + bn * 64 + cB); \
    } while (0)

    MLP_ISSUE(0); cp_commit();
    MLP_ISSUE(1); cp_commit();
    MLP_ISSUE(2); cp_commit();

    for (int it = 0; it < ITERS; it++) {
        cp_wait<2>();
        __syncthreads();
        if (it + 3 < ITERS) MLP_ISSUE(it + 3);
        cp_commit();

        int st = it & 3;
        const unsigned* A = ASb + st * 2560;
        const unsigned* B = BSb + st * 1088;

#pragma unroll
        for (int k8 = 0; k8 < 2; k8++) {
            int kb = k8 * 8;
            unsigned a0[2], a1[2], a2[2], a3[2];
#pragma unroll
            for (int mt = 0; mt < 2; mt++) {
                int r0 = wm * 32 + mt * 16;
                const unsigned* p0 = A + (r0 + g    ) * 20 + kb + t4;
                const unsigned* p1 = A + (r0 + g + 8) * 20 + kb + t4;
                a0[mt] = p0[0]; a2[mt] = p0[4];
                a1[mt] = p1[0]; a3[mt] = p1[4];
            }
#pragma unroll
            for (int nt = 0; nt < 4; nt++) {
                int c0 = wn * 32 + nt * 8;
                unsigned b0 = B[(kb + t4    ) * 68 + c0 + g];
                unsigned b1 = B[(kb + t4 + 4) * 68 + c0 + g];
#pragma unroll
                for (int mt = 0; mt < 2; mt++)
                    mma_tf32(acc[mt][nt][0], acc[mt][nt][1],
                             acc[mt][nt][2], acc[mt][nt][3],
                             a0[mt], a1[mt], a2[mt], a3[mt], b0, b1);
            }
        }
    }

    // epilogue: bias + relu
#pragma unroll
    for (int mt = 0; mt < 2; mt++) {
#pragma unroll
        for (int rr = 0; rr < 2; rr++) {
            long row = rbase + wm * 32 + mt * 16 + g + rr * 8;
#pragma unroll
            for (int nt = 0; nt < 4; nt++) {
                int col = bn * 64 + wn * 32 + nt * 8 + t4 * 2;
                float2 o;
                o.x = fmaxf(acc[mt][nt][rr*2+0] + bias[col    ], 0.f);
                o.y = fmaxf(acc[mt][nt][rr*2+1] + bias[col + 1], 0.f);
                *(float2*)(C + row * DOUT + col) = o;
            }
        }
    }
}

// ---------------------------------------------------------------------------
// tf32 fused score GEMM (a & b) + HardKuma epilogue, cp.async 3-stage.
// grid = (32, 16, 4): block tile 128(t) x 64(s), BK=16, K=256.
// smem: Q[m][k] stride 20 (A-operand), K[s][k] stride 20 (B-operand, n-major
// = direct copy from row-major K). All fragment LDS conflict-free.
// ---------------------------------------------------------------------------
#define ATTN_SMEM_BYTES (3 * (2 * 128*20 + 2 * 64*20) * 4)

__global__ void __launch_bounds__(256) kuma_attn_tf32_kernel(
    const float* __restrict__ Am, const float* __restrict__ Bm,
    const float* __restrict__ dist_emb, float* __restrict__ out)
{
    extern __shared__ unsigned sm[];
    unsigned* QAb = sm;                  // 3 x 128 x 20
    unsigned* QBb = sm + 3 * 2560;       // 3 x 128 x 20
    unsigned* KAb = sm + 6 * 2560;       // 3 x 64 x 20
    unsigned* KBb = sm + 6 * 2560 + 3 * 1280;
    __shared__ float sdist[23];

    int b  = blockIdx.z;
    int bt = blockIdx.y * 128;
    int bs = blockIdx.x * 64;
    int tid = threadIdx.x;
    if (tid < 23) sdist[tid] = dist_emb[tid];

    int wid = tid >> 5, lane = tid & 31;
    int wm  = wid >> 1, wn = wid & 1;
    int g   = lane >> 2, t4 = lane & 3;

    const float* qa = Am + ((long)b * T_SEQ + bt) * DOUT;
    const float* ka = Am + ((long)(8192 + b * T_SEQ) + bs) * DOUT;
    const float* qb = Bm + ((long)b * T_SEQ + bt) * DOUT;
    const float* kb = Bm + ((long)(8192 + b * T_SEQ) + bs) * DOUT;

    // copy coords
    int rQ0 = tid >> 2,         qQ0 = (tid & 3) * 4;
    int rQ1 = (tid + 256) >> 2, qQ1 = ((tid + 256) & 3) * 4;
    int rK = tid >> 2,          qK  = (tid & 3) * 4;   // 64 rows x 4 quads

    float accA[2][4][4], accB[2][4][4];
#pragma unroll
    for (int mt = 0; mt < 2; mt++)
#pragma unroll
        for (int nt = 0; nt < 4; nt++)
#pragma unroll
            for (int c = 0; c < 4; c++) { accA[mt][nt][c] = 0.f; accB[mt][nt][c] = 0.f; }

    const int ITERS = DOUT >> 4;   // 16

#define ATTN_ISSUE(ki) do {                                                  \
        int st_ = (ki) % 3; int k0_ = (ki) << 4;                             \
        unsigned* QA_ = QAb + st_ * 2560;                                    \
        unsigned* QB_ = QBb + st_ * 2560;                                    \
        unsigned* KA_ = KAb + st_ * 1280;                                    \
        unsigned* KB_ = KBb + st_ * 1280;                                    \
        cp16(QA_ + rQ0 * 20 + qQ0, qa + (long)rQ0 * DOUT + k0_ + qQ0);       \
        cp16(QA_ + rQ1 * 20 + qQ1, qa + (long)rQ1 * DOUT + k0_ + qQ1);       \
        cp16(QB_ + rQ0 * 20 + qQ0, qb + (long)rQ0 * DOUT + k0_ + qQ0);       \
        cp16(QB_ + rQ1 * 20 + qQ1, qb + (long)rQ1 * DOUT + k0_ + qQ1);       \
        cp16(KA_ + rK * 20 + qK, ka + (long)rK * DOUT + k0_ + qK);           \
        cp16(KB_ + rK * 20 + qK, kb + (long)rK * DOUT + k0_ + qK);           \
    } while (0)

    ATTN_ISSUE(0); cp_commit();
    ATTN_ISSUE(1); cp_commit();

    for (int it = 0; it < ITERS; it++) {
        cp_wait<1>();
        __syncthreads();
        if (it + 2 < ITERS) ATTN_ISSUE(it + 2);
        cp_commit();

        int st = it % 3;
        const unsigned* QA = QAb + st * 2560;
        const unsigned* QB = QBb + st * 2560;
        const unsigned* KA = KAb + st * 1280;
        const unsigned* KB = KBb + st * 1280;

#pragma unroll
        for (int k8 = 0; k8 < 2; k8++) {
            int kbo = k8 * 8;
            unsigned aA0[2], aA1[2], aA2[2], aA3[2];
            unsigned aB0[2], aB1[2], aB2[2], aB3[2];
#pragma unroll
            for (int mt = 0; mt < 2; mt++) {
                int r0 = wm * 32 + mt * 16;
                const unsigned* p0 = QA + (r0 + g    ) * 20 + kbo + t4;
                const unsigned* p1 = QA + (r0 + g + 8) * 20 + kbo + t4;
                aA0[mt] = p0[0]; aA2[mt] = p0[4];
                aA1[mt] = p1[0]; aA3[mt] = p1[4];
                const unsigned* p2 = QB + (r0 + g    ) * 20 + kbo + t4;
                const unsigned* p3 = QB + (r0 + g + 8) * 20 + kbo + t4;
                aB0[mt] = p2[0]; aB2[mt] = p2[4];
                aB1[mt] = p3[0]; aB3[mt] = p3[4];
            }
#pragma unroll
            for (int nt = 0; nt < 4; nt++) {
                int c0 = wn * 32 + nt * 8;
                const unsigned* pk = KA + (c0 + g) * 20 + kbo + t4;
                unsigned bA0 = pk[0], bA1 = pk[4];
                const unsigned* pk2 = KB + (c0 + g) * 20 + kbo + t4;
                unsigned bB0 = pk2[0], bB1 = pk2[4];
#pragma unroll
                for (int mt = 0; mt < 2; mt++) {
                    mma_tf32(accA[mt][nt][0], accA[mt][nt][1],
                             accA[mt][nt][2], accA[mt][nt][3],
                             aA0[mt], aA1[mt], aA2[mt], aA3[mt], bA0, bA1);
                    mma_tf32(accB[mt][nt][0], accB[mt][nt][1],
                             accB[mt][nt][2], accB[mt][nt][3],
                             aB0[mt], aB1[mt], aB2[mt], aB3[mt], bB0, bB1);
                }
            }
        }
    }

    // HardKuma epilogue + store
#pragma unroll
    for (int mt = 0; mt < 2; mt++) {
#pragma unroll
        for (int rr = 0; rr < 2; rr++) {
            int trow = bt + wm * 32 + mt * 16 + g + rr * 8;
#pragma unroll
            for (int nt = 0; nt < 4; nt++) {
                int scol = bs + wn * 32 + nt * 8 + t4 * 2;
                int rel0 = max(-11, min(11, scol     - trow)) + 11;
                int rel1 = max(-11, min(11, scol + 1 - trow)) + 11;
                float rd0 = sdist[rel0], rd1 = sdist[rel1];
                float2 o;
                o.x = kuma_out(accA[mt][nt][rr*2+0] + rd0, accB[mt][nt][rr*2+0] + rd0);
                o.y = kuma_out(accA[mt][nt][rr*2+1] + rd1, accB[mt][nt][rr*2+1] + rd1);
                *(float2*)(out + ((long)b * T_SEQ + trow) * T_SEQ + scol) = o;
            }
        }
    }
}

// ---------------------------------------------------------------------------
extern "C" void kernel_launch(void* const* d_in, const int* in_sizes, int n_in,
                              void* d_out, int out_size)
{
    const float* q    = (const float*)d_in[0];
    const float* k    = (const float*)d_in[1];
    const float* Wa1  = (const float*)d_in[2];
    const float* ba1  = (const float*)d_in[3];
    const float* Wa2  = (const float*)d_in[4];
    const float* ba2  = (const float*)d_in[5];
    const float* Wb1  = (const float*)d_in[6];
    const float* bb1  = (const float*)d_in[7];
    const float* Wb2  = (const float*)d_in[8];
    const float* bb2  = (const float*)d_in[9];
    const float* dist = (const float*)d_in[10];
    float* out = (float*)d_out;

    float *h1, *h2, *A, *Bm;
    cudaGetSymbolAddress((void**)&h1, g_h1);
    cudaGetSymbolAddress((void**)&h2, g_h2);
    cudaGetSymbolAddress((void**)&A,  g_A);
    cudaGetSymbolAddress((void**)&Bm, g_B);

    static bool attr_set = false;
    if (!attr_set) {
        cudaFuncSetAttribute(mlp_tf32_kernel,
            cudaFuncAttributeMaxDynamicSharedMemorySize, MLP_SMEM_BYTES);
        cudaFuncSetAttribute(kuma_attn_tf32_kernel,
            cudaFuncAttributeMaxDynamicSharedMemorySize, ATTN_SMEM_BYTES);
        attr_set = true;
    }

    dim3 blk(256);
    dim3 g1(8, 128);
    mlp_tf32_kernel<<<g1, blk, MLP_SMEM_BYTES>>>(q, k, Wa1, ba1, h1,
                                                 q, k, Wb1, bb1, h2, DIN);
    mlp_tf32_kernel<<<g1, blk, MLP_SMEM_BYTES>>>(h1, nullptr, Wa2, ba2, A,
                                                 h2, nullptr, Wb2, bb2, Bm, DOUT);

    dim3 g2(T_SEQ / 64, T_SEQ / 128, BATCH);
    kuma_attn_tf32_kernel<<<g2, blk, ATTN_SMEM_BYTES>>>(A, Bm, dist, out);
}

// round 6
// speedup vs baseline: 1.9246x; 1.0639x over previous
#include <cuda_runtime.h>

#define T_SEQ 2048
#define BATCH 4
#define DIN   512
#define DOUT  256
#define NROWS 16384   // 2*BATCH*T_SEQ (q rows then k rows)

// Scratch (static __device__ — no allocation)
__device__ float g_h1[NROWS * DOUT];
__device__ float g_h2[NROWS * DOUT];
__device__ float g_A[NROWS * DOUT];
__device__ float g_B[NROWS * DOUT];

// ---------------------------------------------------------------------------
// helpers
// ---------------------------------------------------------------------------
__device__ __forceinline__ float f_ex2(float x) {
    float y; asm("ex2.approx.ftz.f32 %0, %1;" : "=f"(y) : "f"(x)); return y;
}
__device__ __forceinline__ float f_lg2(float x) {
    float y; asm("lg2.approx.ftz.f32 %0, %1;" : "=f"(y) : "f"(x)); return y;
}
__device__ __forceinline__ float f_rcp(float x) {
    float y; asm("rcp.approx.ftz.f32 %0, %1;" : "=f"(y) : "f"(x)); return y;
}
__device__ __forceinline__ void mma_tf32(
    float& c0, float& c1, float& c2, float& c3,
    unsigned a0, unsigned a1, unsigned a2, unsigned a3,
    unsigned b0, unsigned b1)
{
    asm("mma.sync.aligned.m16n8k8.row.col.f32.tf32.tf32.f32 "
        "{%0,%1,%2,%3}, {%4,%5,%6,%7}, {%8,%9}, {%0,%1,%2,%3};"
        : "+f"(c0), "+f"(c1), "+f"(c2), "+f"(c3)
        : "r"(a0), "r"(a1), "r"(a2), "r"(a3), "r"(b0), "r"(b1));
}
__device__ __forceinline__ void cp16(void* d, const void* s) {
    unsigned a = (unsigned)__cvta_generic_to_shared(d);
    asm volatile("cp.async.cg.shared.global [%0], [%1], 16;" :: "r"(a), "l"(s));
}
__device__ __forceinline__ void cp_commit() {
    asm volatile("cp.async.commit_group;");
}
template<int N> __device__ __forceinline__ void cp_wait() {
    asm volatile("cp.async.wait_group %0;" :: "n"(N));
}

#define LN2   0.69314718056f
#define RLN2  1.44269504089f

__device__ __forceinline__ float softplus_fast(float x) {
    float e = f_ex2(-fabsf(x) * RLN2);
    return fmaxf(x, 0.f) + f_lg2(1.f + e) * LN2;
}

// HardKuma epilogue, fused-Stirling Beta (16 MUFU total)
__device__ __forceinline__ float kuma_out(float ar, float br) {
    const float K_T0 = -3.58496250072f;   // log2(1/12)
    const float K_T1 = -0.12553088208f;   // log2(11/12)
    float a  = fminf(fmaxf(softplus_fast(ar), 0.01f), 100.f);
    float bb = fminf(fmaxf(softplus_fast(br), 0.01f), 100.f);
    float u0 = f_ex2(a * K_T0);
    float u1 = f_ex2(a * K_T1);
    float E0 = f_ex2(bb * f_lg2(1.f - u0));  // 1 - p0
    float p1 = f_ex2(bb * f_lg2(1.f - u1));
    float pc = E0 - p1;

    // mean = bb * Beta(g, bb),  g = 1 + 1/a.
    // lnB = S(y1)+S(y2)-S(y3) + (1/12)(1/y1+1/y2-1/y3) + ln(ps/(pg*pb)),
    // y1=g+4, y2=bb+4, y3=g+bb+4; S(y)=(y-.5)ln y - y + .5 ln 2pi.
    // Linear terms: -y1-y2+y3 = -4 (constant).  Ratio R multiplies outside ex2.
    float g  = 1.f + f_rcp(a);
    float s  = g + bb;
    float y1 = g + 4.f, y2 = bb + 4.f, y3 = s + 4.f;
    float L1 = f_lg2(y1), L2 = f_lg2(y2), L3 = f_lg2(y3);
    float pg = g  * (g  + 1.f) * (g  + 2.f) * (g  + 3.f);
    float pb = bb * (bb + 1.f) * (bb + 2.f) * (bb + 3.f);
    float ps = s  * (s  + 1.f) * (s  + 2.f) * (s  + 3.f);
    float pgb = pg * pb;
    float d3  = y1 * y2 * y3;
    float inv = f_rcp(d3 * pgb);                    // one rcp serves both
    float n   = fmaf(y1, y3, fmaf(y2, y3, -y1 * y2)); // y2*y3 + y1*y3 - y1*y2
    float c   = 0.08333333333f * (n * pgb) * inv;   // (1/12)(1/y1+1/y2-1/y3)
    float R   = ps * d3 * inv;                      // ps / (pg*pb)
    float lm2 = (y1 - 0.5f) * L1 + (y2 - 0.5f) * L2 - (y3 - 0.5f) * L3
              + (c - 3.08106146679f) * RLN2;        // (-4 + .5*ln 2pi + c) in log2
    float mean = bb * R * f_ex2(lm2);
    mean = fminf(fmaxf(fmaf(1.2f, mean, -0.1f), 0.f), 1.f);

    float zo = (1.f - E0 > p1) ? 0.f : 1.f;
    return (pc < 0.5f) ? zo : mean;
}

// ---------------------------------------------------------------------------
// tf32 MLP GEMM, cp.async 4-stage. C[16384,256] = relu(X @ W + bias), dual set.
// grid = (4, 128): x = set*2 + colblock(128). Block tile 128x128, BK=16.
// 8 warps as 2(m)x4(n), warp tile 64x32 (LDS:MMA = 1.5).
// smem: A[m][k] stride 20 (banks 20g+t4 distinct), B[k][n] stride 136
//       (banks 8*t4+g: all 32 distinct).
// ---------------------------------------------------------------------------
#define MLP_STAGE_WORDS (128*20 + 16*136)
#define MLP_SMEM_BYTES  (4 * MLP_STAGE_WORDS * 4)

__global__ void __launch_bounds__(256) mlp_tf32_kernel(
    const float* __restrict__ Xq1, const float* __restrict__ Xk1,
    const float* __restrict__ W1,  const float* __restrict__ bias1, float* __restrict__ C1,
    const float* __restrict__ Xq2, const float* __restrict__ Xk2,
    const float* __restrict__ W2,  const float* __restrict__ bias2, float* __restrict__ C2,
    int K)
{
    extern __shared__ unsigned sm[];
    unsigned* ASb = sm;                    // 4 stages x 128 x 20
    unsigned* BSb = sm + 4 * 2560;         // 4 stages x 16 x 136

    int set = blockIdx.x >> 1;
    int bn  = blockIdx.x & 1;              // 2 col-blocks of 128
    long rbase = (long)blockIdx.y * 128;

    const float* Xq   = set ? Xq2 : Xq1;
    const float* Xk   = set ? Xk2 : Xk1;
    const float* W    = set ? W2  : W1;
    const float* bias = set ? bias2 : bias1;
    float*       C    = set ? C2  : C1;

    const float* X;
    if (Xk != nullptr && rbase >= 8192) X = Xk + (rbase - 8192) * (long)K;
    else                                X = Xq + rbase * (long)K;

    int tid = threadIdx.x;
    int wid = tid >> 5, lane = tid & 31;
    int wm  = wid >> 2, wn = wid & 3;      // 2(m) x 4(n)
    int g   = lane >> 2, t4 = lane & 3;

    // copy coords: A 128x4 quads (512, 2/thread); B 16x32 quads (512, 2/thread)
    int rA0 = tid >> 2,          qA0 = (tid & 3) * 4;
    int rA1 = (tid + 256) >> 2,  qA1 = ((tid + 256) & 3) * 4;
    int kB0 = tid >> 5,          cB0 = (tid & 31) * 4;
    int kB1 = (tid + 256) >> 5,  cB1 = ((tid + 256) & 31) * 4;

    float acc[4][4][4];
#pragma unroll
    for (int mt = 0; mt < 4; mt++)
#pragma unroll
        for (int nt = 0; nt < 4; nt++)
#pragma unroll
            for (int c = 0; c < 4; c++) acc[mt][nt][c] = 0.f;

    const int ITERS = K >> 4;

#define MLP_ISSUE(ki) do {                                                    \
        int st_ = (ki) & 3; int k0_ = (ki) << 4;                              \
        unsigned* A_ = ASb + st_ * 2560;                                      \
        unsigned* B_ = BSb + st_ * 2176;                                      \
        cp16(A_ + rA0 * 20 + qA0, X + (long)rA0 * K + k0_ + qA0);             \
        cp16(A_ + rA1 * 20 + qA1, X + (long)rA1 * K + k0_ + qA1);             \
        cp16(B_ + kB0 * 136 + cB0, W + (long)(k0_ + kB0) * DOUT + bn * 128 + cB0); \
        cp16(B_ + kB1 * 136 + cB1, W + (long)(k0_ + kB1) * DOUT + bn * 128 + cB1); \
    } while (0)

    MLP_ISSUE(0); cp_commit();
    MLP_ISSUE(1); cp_commit();
    MLP_ISSUE(2); cp_commit();

    for (int it = 0; it < ITERS; it++) {
        cp_wait<2>();
        __syncthreads();
        if (it + 3 < ITERS) MLP_ISSUE(it + 3);
        cp_commit();

        int st = it & 3;
        const unsigned* A = ASb + st * 2560;
        const unsigned* B = BSb + st * 2176;

#pragma unroll
        for (int k8 = 0; k8 < 2; k8++) {
            int kb = k8 * 8;
            unsigned a0[4], a1[4], a2[4], a3[4];
#pragma unroll
            for (int mt = 0; mt < 4; mt++) {
                int r0 = wm * 64 + mt * 16;
                const unsigned* p0 = A + (r0 + g    ) * 20 + kb + t4;
                const unsigned* p1 = A + (r0 + g + 8) * 20 + kb + t4;
                a0[mt] = p0[0]; a2[mt] = p0[4];
                a1[mt] = p1[0]; a3[mt] = p1[4];
            }
#pragma unroll
            for (int nt = 0; nt < 4; nt++) {
                int c0 = wn * 32 + nt * 8;
                unsigned b0 = B[(kb + t4    ) * 136 + c0 + g];
                unsigned b1 = B[(kb + t4 + 4) * 136 + c0 + g];
#pragma unroll
                for (int mt = 0; mt < 4; mt++)
                    mma_tf32(acc[mt][nt][0], acc[mt][nt][1],
                             acc[mt][nt][2], acc[mt][nt][3],
                             a0[mt], a1[mt], a2[mt], a3[mt], b0, b1);
            }
        }
    }

    // epilogue: bias + relu
#pragma unroll
    for (int mt = 0; mt < 4; mt++) {
#pragma unroll
        for (int rr = 0; rr < 2; rr++) {
            long row = rbase + wm * 64 + mt * 16 + g + rr * 8;
#pragma unroll
            for (int nt = 0; nt < 4; nt++) {
                int col = bn * 128 + wn * 32 + nt * 8 + t4 * 2;
                float2 o;
                o.x = fmaxf(acc[mt][nt][rr*2+0] + bias[col    ], 0.f);
                o.y = fmaxf(acc[mt][nt][rr*2+1] + bias[col + 1], 0.f);
                *(float2*)(C + row * DOUT + col) = o;
            }
        }
    }
}

// ---------------------------------------------------------------------------
// tf32 fused score GEMM (a & b) + HardKuma epilogue, cp.async 3-stage.
// grid = (32, 16, 4): block tile 128(t) x 64(s), BK=16, K=256.
// ---------------------------------------------------------------------------
#define ATTN_SMEM_BYTES (3 * (2 * 128*20 + 2 * 64*20) * 4)

__global__ void __launch_bounds__(256) kuma_attn_tf32_kernel(
    const float* __restrict__ Am, const float* __restrict__ Bm,
    const float* __restrict__ dist_emb, float* __restrict__ out)
{
    extern __shared__ unsigned sm[];
    unsigned* QAb = sm;                  // 3 x 128 x 20
    unsigned* QBb = sm + 3 * 2560;       // 3 x 128 x 20
    unsigned* KAb = sm + 6 * 2560;       // 3 x 64 x 20
    unsigned* KBb = sm + 6 * 2560 + 3 * 1280;
    __shared__ float sdist[23];

    int b  = blockIdx.z;
    int bt = blockIdx.y * 128;
    int bs = blockIdx.x * 64;
    int tid = threadIdx.x;
    if (tid < 23) sdist[tid] = dist_emb[tid];

    int wid = tid >> 5, lane = tid & 31;
    int wm  = wid >> 1, wn = wid & 1;
    int g   = lane >> 2, t4 = lane & 3;

    const float* qa = Am + ((long)b * T_SEQ + bt) * DOUT;
    const float* ka = Am + ((long)(8192 + b * T_SEQ) + bs) * DOUT;
    const float* qb = Bm + ((long)b * T_SEQ + bt) * DOUT;
    const float* kb = Bm + ((long)(8192 + b * T_SEQ) + bs) * DOUT;

    int rQ0 = tid >> 2,         qQ0 = (tid & 3) * 4;
    int rQ1 = (tid + 256) >> 2, qQ1 = ((tid + 256) & 3) * 4;
    int rK = tid >> 2,          qK  = (tid & 3) * 4;

    float accA[2][4][4], accB[2][4][4];
#pragma unroll
    for (int mt = 0; mt < 2; mt++)
#pragma unroll
        for (int nt = 0; nt < 4; nt++)
#pragma unroll
            for (int c = 0; c < 4; c++) { accA[mt][nt][c] = 0.f; accB[mt][nt][c] = 0.f; }

    const int ITERS = DOUT >> 4;   // 16

#define ATTN_ISSUE(ki) do {                                                  \
        int st_ = (ki) % 3; int k0_ = (ki) << 4;                             \
        unsigned* QA_ = QAb + st_ * 2560;                                    \
        unsigned* QB_ = QBb + st_ * 2560;                                    \
        unsigned* KA_ = KAb + st_ * 1280;                                    \
        unsigned* KB_ = KBb + st_ * 1280;                                    \
        cp16(QA_ + rQ0 * 20 + qQ0, qa + (long)rQ0 * DOUT + k0_ + qQ0);       \
        cp16(QA_ + rQ1 * 20 + qQ1, qa + (long)rQ1 * DOUT + k0_ + qQ1);       \
        cp16(QB_ + rQ0 * 20 + qQ0, qb + (long)rQ0 * DOUT + k0_ + qQ0);       \
        cp16(QB_ + rQ1 * 20 + qQ1, qb + (long)rQ1 * DOUT + k0_ + qQ1);       \
        cp16(KA_ + rK * 20 + qK, ka + (long)rK * DOUT + k0_ + qK);           \
        cp16(KB_ + rK * 20 + qK, kb + (long)rK * DOUT + k0_ + qK);           \
    } while (0)

    ATTN_ISSUE(0); cp_commit();
    ATTN_ISSUE(1); cp_commit();

    for (int it = 0; it < ITERS; it++) {
        cp_wait<1>();
        __syncthreads();
        if (it + 2 < ITERS) ATTN_ISSUE(it + 2);
        cp_commit();

        int st = it % 3;
        const unsigned* QA = QAb + st * 2560;
        const unsigned* QB = QBb + st * 2560;
        const unsigned* KA = KAb + st * 1280;
        const unsigned* KB = KBb + st * 1280;

#pragma unroll
        for (int k8 = 0; k8 < 2; k8++) {
            int kbo = k8 * 8;
            unsigned aA0[2], aA1[2], aA2[2], aA3[2];
            unsigned aB0[2], aB1[2], aB2[2], aB3[2];
#pragma unroll
            for (int mt = 0; mt < 2; mt++) {
                int r0 = wm * 32 + mt * 16;
                const unsigned* p0 = QA + (r0 + g    ) * 20 + kbo + t4;
                const unsigned* p1 = QA + (r0 + g + 8) * 20 + kbo + t4;
                aA0[mt] = p0[0]; aA2[mt] = p0[4];
                aA1[mt] = p1[0]; aA3[mt] = p1[4];
                const unsigned* p2 = QB + (r0 + g    ) * 20 + kbo + t4;
                const unsigned* p3 = QB + (r0 + g + 8) * 20 + kbo + t4;
                aB0[mt] = p2[0]; aB2[mt] = p2[4];
                aB1[mt] = p3[0]; aB3[mt] = p3[4];
            }
#pragma unroll
            for (int nt = 0; nt < 4; nt++) {
                int c0 = wn * 32 + nt * 8;
                const unsigned* pk = KA + (c0 + g) * 20 + kbo + t4;
                unsigned bA0 = pk[0], bA1 = pk[4];
                const unsigned* pk2 = KB + (c0 + g) * 20 + kbo + t4;
                unsigned bB0 = pk2[0], bB1 = pk2[4];
#pragma unroll
                for (int mt = 0; mt < 2; mt++) {
                    mma_tf32(accA[mt][nt][0], accA[mt][nt][1],
                             accA[mt][nt][2], accA[mt][nt][3],
                             aA0[mt], aA1[mt], aA2[mt], aA3[mt], bA0, bA1);
                    mma_tf32(accB[mt][nt][0], accB[mt][nt][1],
                             accB[mt][nt][2], accB[mt][nt][3],
                             aB0[mt], aB1[mt], aB2[mt], aB3[mt], bB0, bB1);
                }
            }
        }
    }

    // HardKuma epilogue + store
#pragma unroll
    for (int mt = 0; mt < 2; mt++) {
#pragma unroll
        for (int rr = 0; rr < 2; rr++) {
            int trow = bt + wm * 32 + mt * 16 + g + rr * 8;
#pragma unroll
            for (int nt = 0; nt < 4; nt++) {
                int scol = bs + wn * 32 + nt * 8 + t4 * 2;
                int rel0 = max(-11, min(11, scol     - trow)) + 11;
                int rel1 = max(-11, min(11, scol + 1 - trow)) + 11;
                float rd0 = sdist[rel0], rd1 = sdist[rel1];
                float2 o;
                o.x = kuma_out(accA[mt][nt][rr*2+0] + rd0, accB[mt][nt][rr*2+0] + rd0);
                o.y = kuma_out(accA[mt][nt][rr*2+1] + rd1, accB[mt][nt][rr*2+1] + rd1);
                *(float2*)(out + ((long)b * T_SEQ + trow) * T_SEQ + scol) = o;
            }
        }
    }
}

// ---------------------------------------------------------------------------
extern "C" void kernel_launch(void* const* d_in, const int* in_sizes, int n_in,
                              void* d_out, int out_size)
{
    const float* q    = (const float*)d_in[0];
    const float* k    = (const float*)d_in[1];
    const float* Wa1  = (const float*)d_in[2];
    const float* ba1  = (const float*)d_in[3];
    const float* Wa2  = (const float*)d_in[4];
    const float* ba2  = (const float*)d_in[5];
    const float* Wb1  = (const float*)d_in[6];
    const float* bb1  = (const float*)d_in[7];
    const float* Wb2  = (const float*)d_in[8];
    const float* bb2  = (const float*)d_in[9];
    const float* dist = (const float*)d_in[10];
    float* out = (float*)d_out;

    float *h1, *h2, *A, *Bm;
    cudaGetSymbolAddress((void**)&h1, g_h1);
    cudaGetSymbolAddress((void**)&h2, g_h2);
    cudaGetSymbolAddress((void**)&A,  g_A);
    cudaGetSymbolAddress((void**)&Bm, g_B);

    static bool attr_set = false;
    if (!attr_set) {
        cudaFuncSetAttribute(mlp_tf32_kernel,
            cudaFuncAttributeMaxDynamicSharedMemorySize, MLP_SMEM_BYTES);
        cudaFuncSetAttribute(kuma_attn_tf32_kernel,
            cudaFuncAttributeMaxDynamicSharedMemorySize, ATTN_SMEM_BYTES);
        attr_set = true;
    }

    dim3 blk(256);
    dim3 g1(4, 128);
    mlp_tf32_kernel<<<g1, blk, MLP_SMEM_BYTES>>>(q, k, Wa1, ba1, h1,
                                                 q, k, Wb1, bb1, h2, DIN);
    mlp_tf32_kernel<<<g1, blk, MLP_SMEM_BYTES>>>(h1, nullptr, Wa2, ba2, A,
                                                 h2, nullptr, Wb2, bb2, Bm, DOUT);

    dim3 g2(T_SEQ / 64, T_SEQ / 128, BATCH);
    kuma_attn_tf32_kernel<<<g2, blk, ATTN_SMEM_BYTES>>>(A, Bm, dist, out);
}

// round 7
// speedup vs baseline: 2.0003x; 1.0393x over previous
#include <cuda_runtime.h>

#define T_SEQ 2048
#define BATCH 4
#define DIN   512
#define DOUT  256
#define NROWS 16384   // 2*BATCH*T_SEQ (q rows then k rows)

// Scratch (static __device__ — no allocation)
__device__ float g_h1[NROWS * DOUT];
__device__ float g_h2[NROWS * DOUT];
__device__ float g_A[NROWS * DOUT];
__device__ float g_B[NROWS * DOUT];

// ---------------------------------------------------------------------------
// helpers
// ---------------------------------------------------------------------------
__device__ __forceinline__ float f_ex2(float x) {
    float y; asm("ex2.approx.ftz.f32 %0, %1;" : "=f"(y) : "f"(x)); return y;
}
__device__ __forceinline__ float f_lg2(float x) {
    float y; asm("lg2.approx.ftz.f32 %0, %1;" : "=f"(y) : "f"(x)); return y;
}
__device__ __forceinline__ float f_rcp(float x) {
    float y; asm("rcp.approx.ftz.f32 %0, %1;" : "=f"(y) : "f"(x)); return y;
}
__device__ __forceinline__ void mma_tf32(
    float& c0, float& c1, float& c2, float& c3,
    unsigned a0, unsigned a1, unsigned a2, unsigned a3,
    unsigned b0, unsigned b1)
{
    asm("mma.sync.aligned.m16n8k8.row.col.f32.tf32.tf32.f32 "
        "{%0,%1,%2,%3}, {%4,%5,%6,%7}, {%8,%9}, {%0,%1,%2,%3};"
        : "+f"(c0), "+f"(c1), "+f"(c2), "+f"(c3)
        : "r"(a0), "r"(a1), "r"(a2), "r"(a3), "r"(b0), "r"(b1));
}
__device__ __forceinline__ void cp16(void* d, const void* s) {
    unsigned a = (unsigned)__cvta_generic_to_shared(d);
    asm volatile("cp.async.cg.shared.global [%0], [%1], 16;" :: "r"(a), "l"(s));
}
__device__ __forceinline__ void cp_commit() {
    asm volatile("cp.async.commit_group;");
}
template<int N> __device__ __forceinline__ void cp_wait() {
    asm volatile("cp.async.wait_group %0;" :: "n"(N));
}

#define LN2   0.69314718056f
#define RLN2  1.44269504089f

__device__ __forceinline__ float softplus_fast(float x) {
    float e = f_ex2(-fabsf(x) * RLN2);
    return fmaxf(x, 0.f) + f_lg2(1.f + e) * LN2;
}

// HardKuma epilogue, fused-Stirling Beta (16 MUFU total)
__device__ __forceinline__ float kuma_out(float ar, float br) {
    const float K_T0 = -3.58496250072f;   // log2(1/12)
    const float K_T1 = -0.12553088208f;   // log2(11/12)
    float a  = fminf(fmaxf(softplus_fast(ar), 0.01f), 100.f);
    float bb = fminf(fmaxf(softplus_fast(br), 0.01f), 100.f);
    float u0 = f_ex2(a * K_T0);
    float u1 = f_ex2(a * K_T1);
    float E0 = f_ex2(bb * f_lg2(1.f - u0));  // 1 - p0
    float p1 = f_ex2(bb * f_lg2(1.f - u1));
    float pc = E0 - p1;

    float g  = 1.f + f_rcp(a);
    float s  = g + bb;
    float y1 = g + 4.f, y2 = bb + 4.f, y3 = s + 4.f;
    float L1 = f_lg2(y1), L2 = f_lg2(y2), L3 = f_lg2(y3);
    float pg = g  * (g  + 1.f) * (g  + 2.f) * (g  + 3.f);
    float pb = bb * (bb + 1.f) * (bb + 2.f) * (bb + 3.f);
    float ps = s  * (s  + 1.f) * (s  + 2.f) * (s  + 3.f);
    float pgb = pg * pb;
    float d3  = y1 * y2 * y3;
    float inv = f_rcp(d3 * pgb);
    float n   = fmaf(y1, y3, fmaf(y2, y3, -y1 * y2));
    float c   = 0.08333333333f * (n * pgb) * inv;
    float R   = ps * d3 * inv;
    float lm2 = (y1 - 0.5f) * L1 + (y2 - 0.5f) * L2 - (y3 - 0.5f) * L3
              + (c - 3.08106146679f) * RLN2;
    float mean = bb * R * f_ex2(lm2);
    mean = fminf(fmaxf(fmaf(1.2f, mean, -0.1f), 0.f), 1.f);

    float zo = (1.f - E0 > p1) ? 0.f : 1.f;
    return (pc < 0.5f) ? zo : mean;
}

// ---------------------------------------------------------------------------
// tf32 MLP GEMM, cp.async 3-stage, BK=32. C = relu(X @ W + bias), dual set.
// grid = (4, 128): x = set*2 + colblock(128). Block tile 128x128.
// 8 warps as 2(m)x4(n), warp tile 64x32.
// smem: A[m][k] stride 36 (banks (4g+t4)%32 distinct), B[k][n] stride 136.
// ---------------------------------------------------------------------------
#define MLP_A_STRIDE 36
#define MLP_A_WORDS  (128 * MLP_A_STRIDE)   // 4608
#define MLP_B_WORDS  (32 * 136)             // 4352
#define MLP_SMEM_BYTES (3 * (MLP_A_WORDS + MLP_B_WORDS) * 4)   // 107520

__global__ void __launch_bounds__(256, 2) mlp_tf32_kernel(
    const float* __restrict__ Xq1, const float* __restrict__ Xk1,
    const float* __restrict__ W1,  const float* __restrict__ bias1, float* __restrict__ C1,
    const float* __restrict__ Xq2, const float* __restrict__ Xk2,
    const float* __restrict__ W2,  const float* __restrict__ bias2, float* __restrict__ C2,
    int K)
{
    extern __shared__ unsigned sm[];
    unsigned* ASb = sm;                          // 3 stages x 128 x 36
    unsigned* BSb = sm + 3 * MLP_A_WORDS;        // 3 stages x 32 x 136

    int set = blockIdx.x >> 1;
    int bn  = blockIdx.x & 1;
    long rbase = (long)blockIdx.y * 128;

    const float* Xq   = set ? Xq2 : Xq1;
    const float* Xk   = set ? Xk2 : Xk1;
    const float* W    = set ? W2  : W1;
    const float* bias = set ? bias2 : bias1;
    float*       C    = set ? C2  : C1;

    const float* X;
    if (Xk != nullptr && rbase >= 8192) X = Xk + (rbase - 8192) * (long)K;
    else                                X = Xq + rbase * (long)K;

    int tid = threadIdx.x;
    int wid = tid >> 5, lane = tid & 31;
    int wm  = wid >> 2, wn = wid & 3;      // 2(m) x 4(n)
    int g   = lane >> 2, t4 = lane & 3;

    // copy coords: A 128 rows x 8 quads (1024, 4/thread); B 32 k x 32 quads (1024, 4/thread)
    int rA[4], qA[4], kB[4], cB[4];
#pragma unroll
    for (int i = 0; i < 4; i++) {
        int idx = tid + i * 256;
        rA[i] = idx >> 3;  qA[i] = (idx & 7) * 4;
        kB[i] = idx >> 5;  cB[i] = (idx & 31) * 4;
    }

    float acc[4][4][4];
#pragma unroll
    for (int mt = 0; mt < 4; mt++)
#pragma unroll
        for (int nt = 0; nt < 4; nt++)
#pragma unroll
            for (int c = 0; c < 4; c++) acc[mt][nt][c] = 0.f;

    const int ITERS = K >> 5;

#define MLP_ISSUE(ki) do {                                                    \
        int st_ = (ki) % 3; int k0_ = (ki) << 5;                              \
        unsigned* A_ = ASb + st_ * MLP_A_WORDS;                               \
        unsigned* B_ = BSb + st_ * MLP_B_WORDS;                               \
        _Pragma("unroll")                                                     \
        for (int i_ = 0; i_ < 4; i_++) {                                      \
            cp16(A_ + rA[i_] * MLP_A_STRIDE + qA[i_],                         \
                 X + (long)rA[i_] * K + k0_ + qA[i_]);                        \
            cp16(B_ + kB[i_] * 136 + cB[i_],                                  \
                 W + (long)(k0_ + kB[i_]) * DOUT + bn * 128 + cB[i_]);        \
        }                                                                     \
    } while (0)

    MLP_ISSUE(0); cp_commit();
    MLP_ISSUE(1); cp_commit();

    for (int it = 0; it < ITERS; it++) {
        cp_wait<1>();
        __syncthreads();
        if (it + 2 < ITERS) MLP_ISSUE(it + 2);
        cp_commit();

        int st = it % 3;
        const unsigned* A = ASb + st * MLP_A_WORDS;
        const unsigned* B = BSb + st * MLP_B_WORDS;

#pragma unroll
        for (int k8 = 0; k8 < 4; k8++) {
            int kb = k8 * 8;
            unsigned a0[4], a1[4], a2[4], a3[4];
#pragma unroll
            for (int mt = 0; mt < 4; mt++) {
                int r0 = wm * 64 + mt * 16;
                const unsigned* p0 = A + (r0 + g    ) * MLP_A_STRIDE + kb + t4;
                const unsigned* p1 = A + (r0 + g + 8) * MLP_A_STRIDE + kb + t4;
                a0[mt] = p0[0]; a2[mt] = p0[4];
                a1[mt] = p1[0]; a3[mt] = p1[4];
            }
#pragma unroll
            for (int nt = 0; nt < 4; nt++) {
                int c0 = wn * 32 + nt * 8;
                unsigned b0 = B[(kb + t4    ) * 136 + c0 + g];
                unsigned b1 = B[(kb + t4 + 4) * 136 + c0 + g];
#pragma unroll
                for (int mt = 0; mt < 4; mt++)
                    mma_tf32(acc[mt][nt][0], acc[mt][nt][1],
                             acc[mt][nt][2], acc[mt][nt][3],
                             a0[mt], a1[mt], a2[mt], a3[mt], b0, b1);
            }
        }
    }

    // epilogue: bias + relu
#pragma unroll
    for (int mt = 0; mt < 4; mt++) {
#pragma unroll
        for (int rr = 0; rr < 2; rr++) {
            long row = rbase + wm * 64 + mt * 16 + g + rr * 8;
#pragma unroll
            for (int nt = 0; nt < 4; nt++) {
                int col = bn * 128 + wn * 32 + nt * 8 + t4 * 2;
                float2 o;
                o.x = fmaxf(acc[mt][nt][rr*2+0] + bias[col    ], 0.f);
                o.y = fmaxf(acc[mt][nt][rr*2+1] + bias[col + 1], 0.f);
                *(float2*)(C + row * DOUT + col) = o;
            }
        }
    }
}

// ---------------------------------------------------------------------------
// tf32 fused score GEMM (a & b) + HardKuma epilogue, cp.async 3-stage.
// grid = (32, 16, 4): block tile 128(t) x 64(s), BK=16, K=256.
// __launch_bounds__(256,2): cap regs 128 so 2 blocks/SM co-reside and the
// serial transcendental epilogue of one block overlaps the other's mainloop.
// ---------------------------------------------------------------------------
#define ATTN_SMEM_BYTES (3 * (2 * 128*20 + 2 * 64*20) * 4)

__global__ void __launch_bounds__(256, 2) kuma_attn_tf32_kernel(
    const float* __restrict__ Am, const float* __restrict__ Bm,
    const float* __restrict__ dist_emb, float* __restrict__ out)
{
    extern __shared__ unsigned sm[];
    unsigned* QAb = sm;                  // 3 x 128 x 20
    unsigned* QBb = sm + 3 * 2560;       // 3 x 128 x 20
    unsigned* KAb = sm + 6 * 2560;       // 3 x 64 x 20
    unsigned* KBb = sm + 6 * 2560 + 3 * 1280;
    __shared__ float sdist[23];

    int b  = blockIdx.z;
    int bt = blockIdx.y * 128;
    int bs = blockIdx.x * 64;
    int tid = threadIdx.x;
    if (tid < 23) sdist[tid] = dist_emb[tid];

    int wid = tid >> 5, lane = tid & 31;
    int wm  = wid >> 1, wn = wid & 1;
    int g   = lane >> 2, t4 = lane & 3;

    const float* qa = Am + ((long)b * T_SEQ + bt) * DOUT;
    const float* ka = Am + ((long)(8192 + b * T_SEQ) + bs) * DOUT;
    const float* qb = Bm + ((long)b * T_SEQ + bt) * DOUT;
    const float* kb = Bm + ((long)(8192 + b * T_SEQ) + bs) * DOUT;

    int rQ0 = tid >> 2,         qQ0 = (tid & 3) * 4;
    int rQ1 = (tid + 256) >> 2, qQ1 = ((tid + 256) & 3) * 4;
    int rK = tid >> 2,          qK  = (tid & 3) * 4;

    float accA[2][4][4], accB[2][4][4];
#pragma unroll
    for (int mt = 0; mt < 2; mt++)
#pragma unroll
        for (int nt = 0; nt < 4; nt++)
#pragma unroll
            for (int c = 0; c < 4; c++) { accA[mt][nt][c] = 0.f; accB[mt][nt][c] = 0.f; }

    const int ITERS = DOUT >> 4;   // 16

#define ATTN_ISSUE(ki) do {                                                  \
        int st_ = (ki) % 3; int k0_ = (ki) << 4;                             \
        unsigned* QA_ = QAb + st_ * 2560;                                    \
        unsigned* QB_ = QBb + st_ * 2560;                                    \
        unsigned* KA_ = KAb + st_ * 1280;                                    \
        unsigned* KB_ = KBb + st_ * 1280;                                    \
        cp16(QA_ + rQ0 * 20 + qQ0, qa + (long)rQ0 * DOUT + k0_ + qQ0);       \
        cp16(QA_ + rQ1 * 20 + qQ1, qa + (long)rQ1 * DOUT + k0_ + qQ1);       \
        cp16(QB_ + rQ0 * 20 + qQ0, qb + (long)rQ0 * DOUT + k0_ + qQ0);       \
        cp16(QB_ + rQ1 * 20 + qQ1, qb + (long)rQ1 * DOUT + k0_ + qQ1);       \
        cp16(KA_ + rK * 20 + qK, ka + (long)rK * DOUT + k0_ + qK);           \
        cp16(KB_ + rK * 20 + qK, kb + (long)rK * DOUT + k0_ + qK);           \
    } while (0)

    ATTN_ISSUE(0); cp_commit();
    ATTN_ISSUE(1); cp_commit();

    for (int it = 0; it < ITERS; it++) {
        cp_wait<1>();
        __syncthreads();
        if (it + 2 < ITERS) ATTN_ISSUE(it + 2);
        cp_commit();

        int st = it % 3;
        const unsigned* QA = QAb + st * 2560;
        const unsigned* QB = QBb + st * 2560;
        const unsigned* KA = KAb + st * 1280;
        const unsigned* KB = KBb + st * 1280;

#pragma unroll
        for (int k8 = 0; k8 < 2; k8++) {
            int kbo = k8 * 8;
            unsigned aA0[2], aA1[2], aA2[2], aA3[2];
            unsigned aB0[2], aB1[2], aB2[2], aB3[2];
#pragma unroll
            for (int mt = 0; mt < 2; mt++) {
                int r0 = wm * 32 + mt * 16;
                const unsigned* p0 = QA + (r0 + g    ) * 20 + kbo + t4;
                const unsigned* p1 = QA + (r0 + g + 8) * 20 + kbo + t4;
                aA0[mt] = p0[0]; aA2[mt] = p0[4];
                aA1[mt] = p1[0]; aA3[mt] = p1[4];
                const unsigned* p2 = QB + (r0 + g    ) * 20 + kbo + t4;
                const unsigned* p3 = QB + (r0 + g + 8) * 20 + kbo + t4;
                aB0[mt] = p2[0]; aB2[mt] = p2[4];
                aB1[mt] = p3[0]; aB3[mt] = p3[4];
            }
#pragma unroll
            for (int nt = 0; nt < 4; nt++) {
                int c0 = wn * 32 + nt * 8;
                const unsigned* pk = KA + (c0 + g) * 20 + kbo + t4;
                unsigned bA0 = pk[0], bA1 = pk[4];
                const unsigned* pk2 = KB + (c0 + g) * 20 + kbo + t4;
                unsigned bB0 = pk2[0], bB1 = pk2[4];
#pragma unroll
                for (int mt = 0; mt < 2; mt++) {
                    mma_tf32(accA[mt][nt][0], accA[mt][nt][1],
                             accA[mt][nt][2], accA[mt][nt][3],
                             aA0[mt], aA1[mt], aA2[mt], aA3[mt], bA0, bA1);
                    mma_tf32(accB[mt][nt][0], accB[mt][nt][1],
                             accB[mt][nt][2], accB[mt][nt][3],
                             aB0[mt], aB1[mt], aB2[mt], aB3[mt], bB0, bB1);
                }
            }
        }
    }

    // HardKuma epilogue + store
#pragma unroll
    for (int mt = 0; mt < 2; mt++) {
#pragma unroll
        for (int rr = 0; rr < 2; rr++) {
            int trow = bt + wm * 32 + mt * 16 + g + rr * 8;
#pragma unroll
            for (int nt = 0; nt < 4; nt++) {
                int scol = bs + wn * 32 + nt * 8 + t4 * 2;
                int rel0 = max(-11, min(11, scol     - trow)) + 11;
                int rel1 = max(-11, min(11, scol + 1 - trow)) + 11;
                float rd0 = sdist[rel0], rd1 = sdist[rel1];
                float2 o;
                o.x = kuma_out(accA[mt][nt][rr*2+0] + rd0, accB[mt][nt][rr*2+0] + rd0);
                o.y = kuma_out(accA[mt][nt][rr*2+1] + rd1, accB[mt][nt][rr*2+1] + rd1);
                *(float2*)(out + ((long)b * T_SEQ + trow) * T_SEQ + scol) = o;
            }
        }
    }
}

// ---------------------------------------------------------------------------
extern "C" void kernel_launch(void* const* d_in, const int* in_sizes, int n_in,
                              void* d_out, int out_size)
{
    const float* q    = (const float*)d_in[0];
    const float* k    = (const float*)d_in[1];
    const float* Wa1  = (const float*)d_in[2];
    const float* ba1  = (const float*)d_in[3];
    const float* Wa2  = (const float*)d_in[4];
    const float* ba2  = (const float*)d_in[5];
    const float* Wb1  = (const float*)d_in[6];
    const float* bb1  = (const float*)d_in[7];
    const float* Wb2  = (const float*)d_in[8];
    const float* bb2  = (const float*)d_in[9];
    const float* dist = (const float*)d_in[10];
    float* out = (float*)d_out;

    float *h1, *h2, *A, *Bm;
    cudaGetSymbolAddress((void**)&h1, g_h1);
    cudaGetSymbolAddress((void**)&h2, g_h2);
    cudaGetSymbolAddress((void**)&A,  g_A);
    cudaGetSymbolAddress((void**)&Bm, g_B);

    static bool attr_set = false;
    if (!attr_set) {
        cudaFuncSetAttribute(mlp_tf32_kernel,
            cudaFuncAttributeMaxDynamicSharedMemorySize, MLP_SMEM_BYTES);
        cudaFuncSetAttribute(kuma_attn_tf32_kernel,
            cudaFuncAttributeMaxDynamicSharedMemorySize, ATTN_SMEM_BYTES);
        attr_set = true;
    }

    dim3 blk(256);
    dim3 g1(4, 128);
    mlp_tf32_kernel<<<g1, blk, MLP_SMEM_BYTES>>>(q, k, Wa1, ba1, h1,
                                                 q, k, Wb1, bb1, h2, DIN);
    mlp_tf32_kernel<<<g1, blk, MLP_SMEM_BYTES>>>(h1, nullptr, Wa2, ba2, A,
                                                 h2, nullptr, Wb2, bb2, Bm, DOUT);

    dim3 g2(T_SEQ / 64, T_SEQ / 128, BATCH);
    kuma_attn_tf32_kernel<<<g2, blk, ATTN_SMEM_BYTES>>>(A, Bm, dist, out);
}

// round 8
// speedup vs baseline: 2.0786x; 1.0391x over previous
#include <cuda_runtime.h>

#define T_SEQ 2048
#define BATCH 4
#define DIN   512
#define DOUT  256
#define NROWS 16384   // 2*BATCH*T_SEQ (q rows then k rows)

// Scratch (static __device__ — no allocation)
__device__ float g_h1[NROWS * DOUT];
__device__ float g_h2[NROWS * DOUT];
__device__ float g_A[NROWS * DOUT];
__device__ float g_B[NROWS * DOUT];
// transposed weights [n][k]
__device__ float g_Wt1a[DOUT * DIN];
__device__ float g_Wt1b[DOUT * DIN];
__device__ float g_Wt2a[DOUT * DOUT];
__device__ float g_Wt2b[DOUT * DOUT];

// ---------------------------------------------------------------------------
// helpers
// ---------------------------------------------------------------------------
__device__ __forceinline__ float f_ex2(float x) {
    float y; asm("ex2.approx.ftz.f32 %0, %1;" : "=f"(y) : "f"(x)); return y;
}
__device__ __forceinline__ float f_lg2(float x) {
    float y; asm("lg2.approx.ftz.f32 %0, %1;" : "=f"(y) : "f"(x)); return y;
}
__device__ __forceinline__ float f_rcp(float x) {
    float y; asm("rcp.approx.ftz.f32 %0, %1;" : "=f"(y) : "f"(x)); return y;
}
__device__ __forceinline__ void mma_tf32(
    float& c0, float& c1, float& c2, float& c3,
    unsigned a0, unsigned a1, unsigned a2, unsigned a3,
    unsigned b0, unsigned b1)
{
    asm("mma.sync.aligned.m16n8k8.row.col.f32.tf32.tf32.f32 "
        "{%0,%1,%2,%3}, {%4,%5,%6,%7}, {%8,%9}, {%0,%1,%2,%3};"
        : "+f"(c0), "+f"(c1), "+f"(c2), "+f"(c3)
        : "r"(a0), "r"(a1), "r"(a2), "r"(a3), "r"(b0), "r"(b1));
}
__device__ __forceinline__ void ldsm_x4(unsigned& r0, unsigned& r1,
                                        unsigned& r2, unsigned& r3, unsigned a) {
    asm volatile("ldmatrix.sync.aligned.m8n8.x4.shared.b16 {%0,%1,%2,%3}, [%4];"
                 : "=r"(r0), "=r"(r1), "=r"(r2), "=r"(r3) : "r"(a));
}
__device__ __forceinline__ void ldsm_x2(unsigned& r0, unsigned& r1, unsigned a) {
    asm volatile("ldmatrix.sync.aligned.m8n8.x2.shared.b16 {%0,%1}, [%2];"
                 : "=r"(r0), "=r"(r1) : "r"(a));
}
__device__ __forceinline__ void cp16(void* d, const void* s) {
    unsigned a = (unsigned)__cvta_generic_to_shared(d);
    asm volatile("cp.async.cg.shared.global [%0], [%1], 16;" :: "r"(a), "l"(s));
}
__device__ __forceinline__ void cp_commit() {
    asm volatile("cp.async.commit_group;");
}
template<int N> __device__ __forceinline__ void cp_wait() {
    asm volatile("cp.async.wait_group %0;" :: "n"(N));
}

#define LN2   0.69314718056f
#define RLN2  1.44269504089f

__device__ __forceinline__ float softplus_fast(float x) {
    float e = f_ex2(-fabsf(x) * RLN2);
    return fmaxf(x, 0.f) + f_lg2(1.f + e) * LN2;
}

// HardKuma epilogue, fused-Stirling Beta
__device__ __forceinline__ float kuma_out(float ar, float br) {
    const float K_T0 = -3.58496250072f;   // log2(1/12)
    const float K_T1 = -0.12553088208f;   // log2(11/12)
    float a  = fminf(fmaxf(softplus_fast(ar), 0.01f), 100.f);
    float bb = fminf(fmaxf(softplus_fast(br), 0.01f), 100.f);
    float u0 = f_ex2(a * K_T0);
    float u1 = f_ex2(a * K_T1);
    float E0 = f_ex2(bb * f_lg2(1.f - u0));  // 1 - p0
    float p1 = f_ex2(bb * f_lg2(1.f - u1));
    float pc = E0 - p1;

    float g  = 1.f + f_rcp(a);
    float s  = g + bb;
    float y1 = g + 4.f, y2 = bb + 4.f, y3 = s + 4.f;
    float L1 = f_lg2(y1), L2 = f_lg2(y2), L3 = f_lg2(y3);
    float pg = g  * (g  + 1.f) * (g  + 2.f) * (g  + 3.f);
    float pb = bb * (bb + 1.f) * (bb + 2.f) * (bb + 3.f);
    float ps = s  * (s  + 1.f) * (s  + 2.f) * (s  + 3.f);
    float pgb = pg * pb;
    float d3  = y1 * y2 * y3;
    float inv = f_rcp(d3 * pgb);
    float n   = fmaf(y1, y3, fmaf(y2, y3, -y1 * y2));
    float c   = 0.08333333333f * (n * pgb) * inv;
    float R   = ps * d3 * inv;
    float lm2 = (y1 - 0.5f) * L1 + (y2 - 0.5f) * L2 - (y3 - 0.5f) * L3
              + (c - 3.08106146679f) * RLN2;
    float mean = bb * R * f_ex2(lm2);
    mean = fminf(fmaxf(fmaf(1.2f, mean, -0.1f), 0.f), 1.f);

    float zo = (1.f - E0 > p1) ? 0.f : 1.f;
    return (pc < 0.5f) ? zo : mean;
}

// ---------------------------------------------------------------------------
// Weight transpose: Wt[n][k] = W[k][n].  z: 0=Wa1, 1=Wb1 (512x256), 2=Wa2,
// 3=Wb2 (256x256). grid (16, 8, 4), block (32, 8).
// ---------------------------------------------------------------------------
__global__ void transpose_w_kernel(
    const float* __restrict__ Wa1, const float* __restrict__ Wb1,
    const float* __restrict__ Wa2, const float* __restrict__ Wb2,
    float* __restrict__ T1a, float* __restrict__ T1b,
    float* __restrict__ T2a, float* __restrict__ T2b)
{
    __shared__ float t[32][33];
    int z = blockIdx.z;
    int K = (z < 2) ? DIN : DOUT;
    if (blockIdx.x * 32 >= K) return;
    const float* S = (z == 0) ? Wa1 : (z == 1) ? Wb1 : (z == 2) ? Wa2 : Wb2;
    float*       D = (z == 0) ? T1a : (z == 1) ? T1b : (z == 2) ? T2a : T2b;

    int kb = blockIdx.x * 32, nb = blockIdx.y * 32;
    int x = threadIdx.x, y = threadIdx.y;
#pragma unroll
    for (int i = 0; i < 32; i += 8)
        t[y + i][x] = S[(long)(kb + y + i) * DOUT + nb + x];
    __syncthreads();
#pragma unroll
    for (int i = 0; i < 32; i += 8)
        D[(long)(nb + y + i) * K + kb + x] = t[x][y + i];
}

// ---------------------------------------------------------------------------
// tf32 MLP GEMM, cp.async 3-stage, BK=32, ldmatrix fragments.
// C[16384,256] = relu(X @ W + bias), dual weight set; W passed TRANSPOSED
// as Wt[n][k] so B tile is n-major in smem (ldmatrix.x2-compatible).
// grid = (4, 128): x = set*2 + colblock(128). Block tile 128x128.
// 8 warps as 2(m)x4(n), warp tile 64x32. smem stride 36 words.
// ---------------------------------------------------------------------------
#define MLP_A_STRIDE 36
#define MLP_A_WORDS  (128 * 36)   // 4608
#define MLP_B_WORDS  (128 * 36)   // 4608 (B tile: 128 n-rows x 32 k)
#define MLP_SMEM_BYTES (3 * (MLP_A_WORDS + MLP_B_WORDS) * 4)   // 110592

__global__ void __launch_bounds__(256, 2) mlp_tf32_kernel(
    const float* __restrict__ Xq1, const float* __restrict__ Xk1,
    const float* __restrict__ Wt1, const float* __restrict__ bias1, float* __restrict__ C1,
    const float* __restrict__ Xq2, const float* __restrict__ Xk2,
    const float* __restrict__ Wt2, const float* __restrict__ bias2, float* __restrict__ C2,
    int K)
{
    extern __shared__ unsigned sm[];
    unsigned* ASb = sm;                          // 3 stages x 128 x 36
    unsigned* BSb = sm + 3 * MLP_A_WORDS;        // 3 stages x 128 x 36

    int set = blockIdx.x >> 1;
    int bn  = blockIdx.x & 1;
    long rbase = (long)blockIdx.y * 128;

    const float* Xq   = set ? Xq2 : Xq1;
    const float* Xk   = set ? Xk2 : Xk1;
    const float* Wt   = set ? Wt2 : Wt1;
    const float* bias = set ? bias2 : bias1;
    float*       C    = set ? C2  : C1;

    const float* X;
    if (Xk != nullptr && rbase >= 8192) X = Xk + (rbase - 8192) * (long)K;
    else                                X = Xq + rbase * (long)K;
    const float* Wb = Wt + (long)(bn * 128) * K;   // 128 n-rows of length K

    int tid = threadIdx.x;
    int wid = tid >> 5, lane = tid & 31;
    int wm  = wid >> 2, wn = wid & 3;      // 2(m) x 4(n)
    int g   = lane >> 2, t4 = lane & 3;

    // copy coords: 128 rows x 8 quads = 1024 chunks, 4/thread (A and B same)
    int rA[4], qA[4];
#pragma unroll
    for (int i = 0; i < 4; i++) {
        int idx = tid + i * 256;
        rA[i] = idx >> 3;  qA[i] = (idx & 7) * 4;
    }

    // ldmatrix lane byte-offsets within a stage
    int l7 = lane & 7, l8 = (lane >> 3) & 1, l16 = (lane >> 4) & 1;
    unsigned aoff = ((wm * 64 + l7 + l8 * 8) * 36 + l16 * 4) * 4;  // +mt*2304
    unsigned boff = ((wn * 32 + l7) * 36 + l8 * 4) * 4;            // +nt*1152
    unsigned aBase = (unsigned)__cvta_generic_to_shared(ASb);
    unsigned bBase = (unsigned)__cvta_generic_to_shared(BSb);

    float acc[4][4][4];
#pragma unroll
    for (int mt = 0; mt < 4; mt++)
#pragma unroll
        for (int nt = 0; nt < 4; nt++)
#pragma unroll
            for (int c = 0; c < 4; c++) acc[mt][nt][c] = 0.f;

    const int ITERS = K >> 5;

#define MLP_ISSUE(ki) do {                                                    \
        int st_ = (ki) % 3; int k0_ = (ki) << 5;                              \
        unsigned* A_ = ASb + st_ * MLP_A_WORDS;                               \
        unsigned* B_ = BSb + st_ * MLP_B_WORDS;                               \
        _Pragma("unroll")                                                     \
        for (int i_ = 0; i_ < 4; i_++) {                                      \
            cp16(A_ + rA[i_] * 36 + qA[i_], X  + (long)rA[i_] * K + k0_ + qA[i_]); \
            cp16(B_ + rA[i_] * 36 + qA[i_], Wb + (long)rA[i_] * K + k0_ + qA[i_]); \
        }                                                                     \
    } while (0)

    MLP_ISSUE(0); cp_commit();
    MLP_ISSUE(1); cp_commit();

    for (int it = 0; it < ITERS; it++) {
        cp_wait<1>();
        __syncthreads();
        if (it + 2 < ITERS) MLP_ISSUE(it + 2);
        cp_commit();

        int st = it % 3;
        unsigned aS = aBase + st * (MLP_A_WORDS * 4);
        unsigned bS = bBase + st * (MLP_B_WORDS * 4);

#pragma unroll
        for (int k8 = 0; k8 < 4; k8++) {
            unsigned kbyte = k8 * 32;
            unsigned a0[4], a1[4], a2[4], a3[4];
#pragma unroll
            for (int mt = 0; mt < 4; mt++)
                ldsm_x4(a0[mt], a1[mt], a2[mt], a3[mt],
                        aS + aoff + mt * 2304 + kbyte);
#pragma unroll
            for (int nt = 0; nt < 4; nt++) {
                unsigned b0, b1;
                ldsm_x2(b0, b1, bS + boff + nt * 1152 + kbyte);
#pragma unroll
                for (int mt = 0; mt < 4; mt++)
                    mma_tf32(acc[mt][nt][0], acc[mt][nt][1],
                             acc[mt][nt][2], acc[mt][nt][3],
                             a0[mt], a1[mt], a2[mt], a3[mt], b0, b1);
            }
        }
    }

    // epilogue: bias + relu
#pragma unroll
    for (int mt = 0; mt < 4; mt++) {
#pragma unroll
        for (int rr = 0; rr < 2; rr++) {
            long row = rbase + wm * 64 + mt * 16 + g + rr * 8;
#pragma unroll
            for (int nt = 0; nt < 4; nt++) {
                int col = bn * 128 + wn * 32 + nt * 8 + t4 * 2;
                float2 o;
                o.x = fmaxf(acc[mt][nt][rr*2+0] + bias[col    ], 0.f);
                o.y = fmaxf(acc[mt][nt][rr*2+1] + bias[col + 1], 0.f);
                *(float2*)(C + row * DOUT + col) = o;
            }
        }
    }
}

// ---------------------------------------------------------------------------
// tf32 fused score GEMM (a & b) + HardKuma epilogue, cp.async 3-stage,
// ldmatrix fragments. grid = (32, 16, 4): tile 128(t) x 64(s), BK=16, K=256.
// ---------------------------------------------------------------------------
#define ATTN_SMEM_BYTES (3 * (2 * 128*20 + 2 * 64*20) * 4)

__global__ void __launch_bounds__(256, 2) kuma_attn_tf32_kernel(
    const float* __restrict__ Am, const float* __restrict__ Bm,
    const float* __restrict__ dist_emb, float* __restrict__ out)
{
    extern __shared__ unsigned sm[];
    unsigned* QAb = sm;                  // 3 x 128 x 20
    unsigned* QBb = sm + 3 * 2560;       // 3 x 128 x 20
    unsigned* KAb = sm + 6 * 2560;       // 3 x 64 x 20
    unsigned* KBb = sm + 6 * 2560 + 3 * 1280;
    __shared__ float sdist[23];

    int b  = blockIdx.z;
    int bt = blockIdx.y * 128;
    int bs = blockIdx.x * 64;
    int tid = threadIdx.x;
    if (tid < 23) sdist[tid] = dist_emb[tid];

    int wid = tid >> 5, lane = tid & 31;
    int wm  = wid >> 1, wn = wid & 1;
    int g   = lane >> 2, t4 = lane & 3;

    const float* qa = Am + ((long)b * T_SEQ + bt) * DOUT;
    const float* ka = Am + ((long)(8192 + b * T_SEQ) + bs) * DOUT;
    const float* qb = Bm + ((long)b * T_SEQ + bt) * DOUT;
    const float* kb = Bm + ((long)(8192 + b * T_SEQ) + bs) * DOUT;

    int rQ0 = tid >> 2,         qQ0 = (tid & 3) * 4;
    int rQ1 = (tid + 256) >> 2, qQ1 = ((tid + 256) & 3) * 4;
    int rK = tid >> 2,          qK  = (tid & 3) * 4;

    // ldmatrix lane byte-offsets
    int l7 = lane & 7, l8 = (lane >> 3) & 1, l16 = (lane >> 4) & 1;
    unsigned aoff = ((wm * 32 + l7 + l8 * 8) * 20 + l16 * 4) * 4;  // +mt*1280
    unsigned boff = ((wn * 32 + l7) * 20 + l8 * 4) * 4;            // +nt*640
    unsigned qaB = (unsigned)__cvta_generic_to_shared(QAb);
    unsigned qbB = (unsigned)__cvta_generic_to_shared(QBb);
    unsigned kaB = (unsigned)__cvta_generic_to_shared(KAb);
    unsigned kbB = (unsigned)__cvta_generic_to_shared(KBb);

    float accA[2][4][4], accB[2][4][4];
#pragma unroll
    for (int mt = 0; mt < 2; mt++)
#pragma unroll
        for (int nt = 0; nt < 4; nt++)
#pragma unroll
            for (int c = 0; c < 4; c++) { accA[mt][nt][c] = 0.f; accB[mt][nt][c] = 0.f; }

    const int ITERS = DOUT >> 4;   // 16

#define ATTN_ISSUE(ki) do {                                                  \
        int st_ = (ki) % 3; int k0_ = (ki) << 4;                             \
        unsigned* QA_ = QAb + st_ * 2560;                                    \
        unsigned* QB_ = QBb + st_ * 2560;                                    \
        unsigned* KA_ = KAb + st_ * 1280;                                    \
        unsigned* KB_ = KBb + st_ * 1280;                                    \
        cp16(QA_ + rQ0 * 20 + qQ0, qa + (long)rQ0 * DOUT + k0_ + qQ0);       \
        cp16(QA_ + rQ1 * 20 + qQ1, qa + (long)rQ1 * DOUT + k0_ + qQ1);       \
        cp16(QB_ + rQ0 * 20 + qQ0, qb + (long)rQ0 * DOUT + k0_ + qQ0);       \
        cp16(QB_ + rQ1 * 20 + qQ1, qb + (long)rQ1 * DOUT + k0_ + qQ1);       \
        cp16(KA_ + rK * 20 + qK, ka + (long)rK * DOUT + k0_ + qK);           \
        cp16(KB_ + rK * 20 + qK, kb + (long)rK * DOUT + k0_ + qK);           \
    } while (0)

    ATTN_ISSUE(0); cp_commit();
    ATTN_ISSUE(1); cp_commit();

    for (int it = 0; it < ITERS; it++) {
        cp_wait<1>();
        __syncthreads();
        if (it + 2 < ITERS) ATTN_ISSUE(it + 2);
        cp_commit();

        int st = it % 3;
        unsigned qaS = qaB + st * (2560 * 4);
        unsigned qbS = qbB + st * (2560 * 4);
        unsigned kaS = kaB + st * (1280 * 4);
        unsigned kbS = kbB + st * (1280 * 4);

#pragma unroll
        for (int k8 = 0; k8 < 2; k8++) {
            unsigned kbyte = k8 * 32;
            unsigned aA0[2], aA1[2], aA2[2], aA3[2];
            unsigned aB0[2], aB1[2], aB2[2], aB3[2];
#pragma unroll
            for (int mt = 0; mt < 2; mt++) {
                ldsm_x4(aA0[mt], aA1[mt], aA2[mt], aA3[mt],
                        qaS + aoff + mt * 1280 + kbyte);
                ldsm_x4(aB0[mt], aB1[mt], aB2[mt], aB3[mt],
                        qbS + aoff + mt * 1280 + kbyte);
            }
#pragma unroll
            for (int nt = 0; nt < 4; nt++) {
                unsigned bA0, bA1, bB0, bB1;
                ldsm_x2(bA0, bA1, kaS + boff + nt * 640 + kbyte);
                ldsm_x2(bB0, bB1, kbS + boff + nt * 640 + kbyte);
#pragma unroll
                for (int mt = 0; mt < 2; mt++) {
                    mma_tf32(accA[mt][nt][0], accA[mt][nt][1],
                             accA[mt][nt][2], accA[mt][nt][3],
                             aA0[mt], aA1[mt], aA2[mt], aA3[mt], bA0, bA1);
                    mma_tf32(accB[mt][nt][0], accB[mt][nt][1],
                             accB[mt][nt][2], accB[mt][nt][3],
                             aB0[mt], aB1[mt], aB2[mt], aB3[mt], bB0, bB1);
                }
            }
        }
    }

    // HardKuma epilogue + store
#pragma unroll
    for (int mt = 0; mt < 2; mt++) {
#pragma unroll
        for (int rr = 0; rr < 2; rr++) {
            int trow = bt + wm * 32 + mt * 16 + g + rr * 8;
#pragma unroll
            for (int nt = 0; nt < 4; nt++) {
                int scol = bs + wn * 32 + nt * 8 + t4 * 2;
                int rel0 = max(-11, min(11, scol     - trow)) + 11;
                int rel1 = max(-11, min(11, scol + 1 - trow)) + 11;
                float rd0 = sdist[rel0], rd1 = sdist[rel1];
                float2 o;
                o.x = kuma_out(accA[mt][nt][rr*2+0] + rd0, accB[mt][nt][rr*2+0] + rd0);
                o.y = kuma_out(accA[mt][nt][rr*2+1] + rd1, accB[mt][nt][rr*2+1] + rd1);
                *(float2*)(out + ((long)b * T_SEQ + trow) * T_SEQ + scol) = o;
            }
        }
    }
}

// ---------------------------------------------------------------------------
extern "C" void kernel_launch(void* const* d_in, const int* in_sizes, int n_in,
                              void* d_out, int out_size)
{
    const float* q    = (const float*)d_in[0];
    const float* k    = (const float*)d_in[1];
    const float* Wa1  = (const float*)d_in[2];
    const float* ba1  = (const float*)d_in[3];
    const float* Wa2  = (const float*)d_in[4];
    const float* ba2  = (const float*)d_in[5];
    const float* Wb1  = (const float*)d_in[6];
    const float* bb1  = (const float*)d_in[7];
    const float* Wb2  = (const float*)d_in[8];
    const float* bb2  = (const float*)d_in[9];
    const float* dist = (const float*)d_in[10];
    float* out = (float*)d_out;

    float *h1, *h2, *A, *Bm, *t1a, *t1b, *t2a, *t2b;
    cudaGetSymbolAddress((void**)&h1,  g_h1);
    cudaGetSymbolAddress((void**)&h2,  g_h2);
    cudaGetSymbolAddress((void**)&A,   g_A);
    cudaGetSymbolAddress((void**)&Bm,  g_B);
    cudaGetSymbolAddress((void**)&t1a, g_Wt1a);
    cudaGetSymbolAddress((void**)&t1b, g_Wt1b);
    cudaGetSymbolAddress((void**)&t2a, g_Wt2a);
    cudaGetSymbolAddress((void**)&t2b, g_Wt2b);

    cudaFuncSetAttribute(mlp_tf32_kernel,
        cudaFuncAttributeMaxDynamicSharedMemorySize, MLP_SMEM_BYTES);
    cudaFuncSetAttribute(kuma_attn_tf32_kernel,
        cudaFuncAttributeMaxDynamicSharedMemorySize, ATTN_SMEM_BYTES);

    // transpose all 4 weight matrices into [n][k]
    transpose_w_kernel<<<dim3(16, 8, 4), dim3(32, 8)>>>(
        Wa1, Wb1, Wa2, Wb2, t1a, t1b, t2a, t2b);

    dim3 blk(256);
    dim3 g1(4, 128);
    mlp_tf32_kernel<<<g1, blk, MLP_SMEM_BYTES>>>(q, k, t1a, ba1, h1,
                                                 q, k, t1b, bb1, h2, DIN);
    mlp_tf32_kernel<<<g1, blk, MLP_SMEM_BYTES>>>(h1, nullptr, t2a, ba2, A,
                                                 h2, nullptr, t2b, bb2, Bm, DOUT);

    dim3 g2(T_SEQ / 64, T_SEQ / 128, BATCH);
    kuma_attn_tf32_kernel<<<g2, blk, ATTN_SMEM_BYTES>>>(A, Bm, dist, out);
}